// round 3
// baseline (speedup 1.0000x reference)
#include <cuda_runtime.h>
#include <math.h>
#include <float.h>

#define B_   2
#define NPTS 2048
#define C_   256
#define KNB  32
#define HID  512
#define CPH  32
#define M1   (B_*NPTS)        // 4096
#define M2   (B_*NPTS*KNB)    // 131072
#define EPSB 1e-5f

// ---------------- device scratch (static allocation, allowed) ----------------
__device__ float g_q[M1*C_];
__device__ float g_k[M1*C_];
__device__ float g_v[M1*C_];
__device__ float g_tmp[M1*HID];
__device__ float g_sq[M1];
__device__ float g_dist[(size_t)B_*NPTS*NPTS];
__device__ int   g_idx[M2];
__device__ float g_big0[(size_t)M2*C_];   // masked_pos, then reused as vecin
__device__ float g_big1[(size_t)M2*C_];   // posb raw
__device__ float g_big2[(size_t)M2*C_];   // value
__device__ float g_s1[(size_t)M2*CPH];
__device__ float g_s2[(size_t)M2*CPH];
__device__ float g_xattn[M1*C_];
__device__ float g_h[M1*HID];
__device__ double g_dsum[HID];
__device__ double g_dsum2[HID];
__device__ float g_mean[HID];
__device__ float g_var[HID];

// ---------------- generic GEMM: C[m,n] = sum_k A[m,k]*W[n,k] ----------------
__global__ __launch_bounds__(256)
void gemm_tn_kernel(const float* __restrict__ A, const float* __restrict__ W,
                    float* __restrict__ C, int M, int N, int K)
{
    __shared__ float As[16][64];
    __shared__ float Bs[16][64];
    int tid = threadIdx.x;
    int tx = tid & 15, ty = tid >> 4;
    int m0 = blockIdx.y * 64, n0 = blockIdx.x * 64;
    float acc[4][4] = {};

    for (int k0 = 0; k0 < K; k0 += 16) {
        #pragma unroll
        for (int i = 0; i < 4; i++) {
            int e = tid + i * 256;
            int r = e >> 4, c = e & 15;
            int gm = m0 + r, gk = k0 + c;
            As[c][r] = (gm < M && gk < K) ? A[(size_t)gm * K + gk] : 0.f;
            int gn = n0 + r;
            Bs[c][r] = (gn < N && gk < K) ? W[(size_t)gn * K + gk] : 0.f;
        }
        __syncthreads();
        #pragma unroll
        for (int kk = 0; kk < 16; kk++) {
            float a[4], b[4];
            #pragma unroll
            for (int i = 0; i < 4; i++) a[i] = As[kk][ty * 4 + i];
            #pragma unroll
            for (int j = 0; j < 4; j++) b[j] = Bs[kk][tx * 4 + j];
            #pragma unroll
            for (int i = 0; i < 4; i++)
                #pragma unroll
                for (int j = 0; j < 4; j++)
                    acc[i][j] += a[i] * b[j];
        }
        __syncthreads();
    }
    #pragma unroll
    for (int i = 0; i < 4; i++) {
        int gm = m0 + ty * 4 + i;
        if (gm >= M) continue;
        #pragma unroll
        for (int j = 0; j < 4; j++) {
            int gn = n0 + tx * 4 + j;
            if (gn < N) C[(size_t)gm * N + gn] = acc[i][j];
        }
    }
}

// ---------------- dist = sq[n] + sq[m] - 2*key_n.key_m  (per batch) ----------------
__global__ __launch_bounds__(256)
void dist_kernel(const float* __restrict__ key, const float* __restrict__ sq,
                 float* __restrict__ dist)
{
    int b = blockIdx.z;
    const float* A  = key + (size_t)b * NPTS * C_;
    const float* sb = sq + b * NPTS;
    float* D = dist + (size_t)b * NPTS * NPTS;

    __shared__ float As[16][64];
    __shared__ float Bs[16][64];
    int tid = threadIdx.x;
    int tx = tid & 15, ty = tid >> 4;
    int m0 = blockIdx.y * 64, n0 = blockIdx.x * 64;
    float acc[4][4] = {};

    for (int k0 = 0; k0 < C_; k0 += 16) {
        #pragma unroll
        for (int i = 0; i < 4; i++) {
            int e = tid + i * 256;
            int r = e >> 4, c = e & 15;
            As[c][r] = A[(size_t)(m0 + r) * C_ + k0 + c];
            Bs[c][r] = A[(size_t)(n0 + r) * C_ + k0 + c];
        }
        __syncthreads();
        #pragma unroll
        for (int kk = 0; kk < 16; kk++) {
            float a[4], bb[4];
            #pragma unroll
            for (int i = 0; i < 4; i++) a[i] = As[kk][ty * 4 + i];
            #pragma unroll
            for (int j = 0; j < 4; j++) bb[j] = Bs[kk][tx * 4 + j];
            #pragma unroll
            for (int i = 0; i < 4; i++)
                #pragma unroll
                for (int j = 0; j < 4; j++)
                    acc[i][j] += a[i] * bb[j];
        }
        __syncthreads();
    }
    #pragma unroll
    for (int i = 0; i < 4; i++) {
        int gm = m0 + ty * 4 + i;
        float sm = sb[gm];
        #pragma unroll
        for (int j = 0; j < 4; j++) {
            int gn = n0 + tx * 4 + j;
            D[(size_t)gm * NPTS + gn] = sm + sb[gn] - 2.f * acc[i][j];
        }
    }
}

// ---------------- sq[row] = sum_d key[row,d]^2 (warp per row) ----------------
__global__ void sq_kernel(const float* __restrict__ key, float* __restrict__ sq)
{
    int w = (blockIdx.x * blockDim.x + threadIdx.x) >> 5;
    int lane = threadIdx.x & 31;
    if (w < M1) {
        const float* p = key + (size_t)w * C_;
        float s = 0.f;
        for (int d = lane; d < C_; d += 32) { float v = p[d]; s += v * v; }
        #pragma unroll
        for (int o = 16; o; o >>= 1) s += __shfl_down_sync(0xffffffffu, s, o);
        if (lane == 0) sq[w] = s;
    }
}

// ---------------- top-32 smallest per row, tie-break smaller index ----------------
__global__ __launch_bounds__(256)
void topk_kernel(const float* __restrict__ dist)
{
    int bn = blockIdx.x;
    const float* row = dist + (size_t)bn * NPTS;
    __shared__ float sv[NPTS];
    __shared__ float rv[256];
    __shared__ int   ri[256];
    int t = threadIdx.x;
    for (int j = t; j < NPTS; j += 256) sv[j] = row[j];
    __syncthreads();

    for (int sel = 0; sel < KNB; sel++) {
        float best = FLT_MAX; int bi = 1 << 30;
        for (int j = t; j < NPTS; j += 256) {
            float v = sv[j];
            if (v < best || (v == best && j < bi)) { best = v; bi = j; }
        }
        rv[t] = best; ri[t] = bi;
        __syncthreads();
        for (int s = 128; s > 0; s >>= 1) {
            if (t < s) {
                if (rv[t + s] < rv[t] || (rv[t + s] == rv[t] && ri[t + s] < ri[t])) {
                    rv[t] = rv[t + s]; ri[t] = ri[t + s];
                }
            }
            __syncthreads();
        }
        if (t == 0) {
            g_idx[(size_t)bn * KNB + sel] = ri[0];
            sv[ri[0]] = FLT_MAX;
        }
        __syncthreads();
    }
}

// ---------------- per-channel batch stats ----------------
__global__ void zero_stats_kernel(int D)
{
    int i = blockIdx.x * blockDim.x + threadIdx.x;
    if (i < D) { g_dsum[i] = 0.0; g_dsum2[i] = 0.0; }
}

__global__ void stats_partial_kernel(const float* __restrict__ Y, int M, int D)
{
    int d = blockIdx.x * 32 + threadIdx.x;
    int stride = gridDim.y * blockDim.y;
    float s = 0.f, s2 = 0.f;
    if (d < D) {
        for (int i = blockIdx.y * blockDim.y + threadIdx.y; i < M; i += stride) {
            float v = Y[(size_t)i * D + d];
            s += v; s2 += v * v;
        }
    }
    __shared__ float sh[8][32], sh2[8][32];
    sh[threadIdx.y][threadIdx.x]  = s;
    sh2[threadIdx.y][threadIdx.x] = s2;
    __syncthreads();
    if (threadIdx.y == 0 && d < D) {
        double ts = 0.0, ts2 = 0.0;
        #pragma unroll
        for (int r = 0; r < 8; r++) { ts += sh[r][threadIdx.x]; ts2 += sh2[r][threadIdx.x]; }
        atomicAdd(&g_dsum[d], ts);
        atomicAdd(&g_dsum2[d], ts2);
    }
}

__global__ void stats_finalize_kernel(int M, int D)
{
    int d = blockIdx.x * blockDim.x + threadIdx.x;
    if (d < D) {
        double m = g_dsum[d] / (double)M;
        double v = g_dsum2[d] / (double)M - m * m;
        g_mean[d] = (float)m;
        g_var[d]  = (float)(v < 0.0 ? 0.0 : v);
    }
}

// ---------------- BN + activations ----------------
__global__ void bn_leaky_kernel(const float* __restrict__ Y, const float* __restrict__ gamma,
                                const float* __restrict__ beta, float* __restrict__ out,
                                int D, size_t total)
{
    size_t e = (size_t)blockIdx.x * blockDim.x + threadIdx.x;
    if (e < total) {
        int d = (int)(e % D);
        float z = (Y[e] - g_mean[d]) * rsqrtf(g_var[d] + EPSB) * gamma[d] + beta[d];
        out[e] = z >= 0.f ? z : 0.2f * z;
    }
}

__global__ void bn_silu_kernel(const float* __restrict__ Y, const float* __restrict__ gamma,
                               const float* __restrict__ beta, float* __restrict__ out,
                               int D, size_t total)
{
    size_t e = (size_t)blockIdx.x * blockDim.x + threadIdx.x;
    if (e < total) {
        int d = (int)(e % D);
        float z = (Y[e] - g_mean[d]) * rsqrtf(g_var[d] + EPSB) * gamma[d] + beta[d];
        out[e] = z / (1.f + expf(-z));
    }
}

__global__ void bn_silu_res_kernel(const float* __restrict__ Y, const float* __restrict__ gamma,
                                   const float* __restrict__ beta, const float* __restrict__ res,
                                   float* __restrict__ out, int D, size_t total)
{
    size_t e = (size_t)blockIdx.x * blockDim.x + threadIdx.x;
    if (e < total) {
        int d = (int)(e % D);
        float z = (Y[e] - g_mean[d]) * rsqrtf(g_var[d] + EPSB) * gamma[d] + beta[d];
        out[e] = res[e] + z / (1.f + expf(-z));
    }
}

// ---------------- masked_pos gather ----------------
__global__ void mpos_kernel(const float* __restrict__ pos)
{
    size_t e = (size_t)blockIdx.x * blockDim.x + threadIdx.x;
    const size_t total = (size_t)M2 * C_;
    if (e < total) {
        int d = (int)(e & (C_ - 1));
        size_t m = e >> 8;              // (b*N+n)*K + k
        int bn = (int)(m >> 5);         // b*N+n
        int b  = bn >> 11;              // /2048
        int j  = g_idx[m];
        g_big0[e] = pos[((size_t)(b * NPTS + j)) * C_ + d] - pos[(size_t)bn * C_ + d];
    }
}

// ---------------- posb BN/leaky + value/vecin combine ----------------
__global__ void posb_combine_kernel(const float* __restrict__ gpb, const float* __restrict__ bpb)
{
    size_t e = (size_t)blockIdx.x * blockDim.x + threadIdx.x;
    const size_t total = (size_t)M2 * C_;
    if (e < total) {
        int d = (int)(e & (C_ - 1));
        size_t m = e >> 8;
        int bn = (int)(m >> 5);
        int b  = bn >> 11;
        int j  = g_idx[m];
        size_t nb = ((size_t)(b * NPTS + j)) * C_ + d;
        float p = (g_big1[e] - g_mean[d]) * rsqrtf(g_var[d] + EPSB) * gpb[d] + bpb[d];
        p = p >= 0.f ? p : 0.2f * p;
        g_big2[e] = g_v[nb] + p;                                   // value
        g_big0[e] = g_k[nb] - g_q[(size_t)bn * C_ + d] + p;        // vecin (reuse)
    }
}

// ---------------- softmax over k + attention + residual ----------------
__global__ __launch_bounds__(256)
void attn_kernel(const float* __restrict__ x, float* __restrict__ xattn)
{
    int bn = blockIdx.x;
    int t = threadIdx.x;
    __shared__ float sv[KNB][CPH];
    __shared__ float soft[KNB][CPH];
    size_t base = (size_t)bn * KNB * CPH;
    for (int e = t; e < KNB * CPH; e += 256)
        sv[e >> 5][e & 31] = g_s2[base + e];
    __syncthreads();
    if (t < CPH) {
        int g = t;
        float mx = -FLT_MAX;
        #pragma unroll
        for (int k = 0; k < KNB; k++) mx = fmaxf(mx, sv[k][g]);
        float s = 0.f;
        #pragma unroll
        for (int k = 0; k < KNB; k++) { float ev = expf(sv[k][g] - mx); soft[k][g] = ev; s += ev; }
        float inv = 1.f / s;
        #pragma unroll
        for (int k = 0; k < KNB; k++) soft[k][g] *= inv;
    }
    __syncthreads();
    // t = output channel c in [0,256)
    int g = t >> 3;
    const float* vrow = g_big2 + (size_t)bn * KNB * C_;
    float acc = 0.f;
    #pragma unroll
    for (int k = 0; k < KNB; k++) acc += vrow[(size_t)k * C_ + t] * soft[k][g];
    size_t o = (size_t)bn * C_ + t;
    xattn[o] = x[o] + acc;
}

// ---------------- host-side helpers ----------------
static inline void run_stats(const float* Y, int M, int D, int splits)
{
    zero_stats_kernel<<<(D + 255) / 256, 256>>>(D);
    dim3 grid((D + 31) / 32, splits);
    dim3 blk(32, 8);
    stats_partial_kernel<<<grid, blk>>>(Y, M, D);
    stats_finalize_kernel<<<(D + 255) / 256, 256>>>(M, D);
}

static inline void run_gemm(const float* A, const float* W, float* C, int M, int N, int K)
{
    dim3 grid((N + 63) / 64, (M + 63) / 64);
    gemm_tn_kernel<<<grid, 256>>>(A, W, C, M, N, K);
}

extern "C" void kernel_launch(void* const* d_in, const int* in_sizes, int n_in,
                              void* d_out, int out_size)
{
    const float* x   = (const float*)d_in[0];
    const float* pos = (const float*)d_in[1];
    const float* Wq  = (const float*)d_in[2];
    const float* gq  = (const float*)d_in[3];
    const float* bq  = (const float*)d_in[4];
    const float* Wk  = (const float*)d_in[5];
    const float* gk  = (const float*)d_in[6];
    const float* bk  = (const float*)d_in[7];
    const float* Wv  = (const float*)d_in[8];
    const float* gv  = (const float*)d_in[9];
    const float* bv  = (const float*)d_in[10];
    const float* Wpb = (const float*)d_in[11];
    const float* gpb = (const float*)d_in[12];
    const float* bpb = (const float*)d_in[13];
    const float* We1 = (const float*)d_in[14];
    const float* ge1 = (const float*)d_in[15];
    const float* be1 = (const float*)d_in[16];
    const float* We2 = (const float*)d_in[17];
    const float* ge2 = (const float*)d_in[18];
    const float* be2 = (const float*)d_in[19];
    const float* Wm1 = (const float*)d_in[20];
    const float* gm1 = (const float*)d_in[21];
    const float* bm1 = (const float*)d_in[22];
    const float* Wm2 = (const float*)d_in[23];
    const float* gm2 = (const float*)d_in[24];
    const float* bm2 = (const float*)d_in[25];
    float* out = (float*)d_out;

    void* p;
    float *q, *k, *v, *tmp, *sqb, *dist, *big0, *big1, *s1, *s2, *xatt, *hbuf;
    cudaGetSymbolAddress(&p, g_q);     q    = (float*)p;
    cudaGetSymbolAddress(&p, g_k);     k    = (float*)p;
    cudaGetSymbolAddress(&p, g_v);     v    = (float*)p;
    cudaGetSymbolAddress(&p, g_tmp);   tmp  = (float*)p;
    cudaGetSymbolAddress(&p, g_sq);    sqb  = (float*)p;
    cudaGetSymbolAddress(&p, g_dist);  dist = (float*)p;
    cudaGetSymbolAddress(&p, g_big0);  big0 = (float*)p;
    cudaGetSymbolAddress(&p, g_big1);  big1 = (float*)p;
    cudaGetSymbolAddress(&p, g_s1);    s1   = (float*)p;
    cudaGetSymbolAddress(&p, g_s2);    s2   = (float*)p;
    cudaGetSymbolAddress(&p, g_xattn); xatt = (float*)p;
    cudaGetSymbolAddress(&p, g_h);     hbuf = (float*)p;

    const size_t tot1  = (size_t)M1 * C_;
    const size_t totB  = (size_t)M2 * C_;
    const size_t totS  = (size_t)M2 * CPH;
    const int BLK = 256;

    // ---- q, key, val = conv1(x, W*, g*, b*) ----
    run_gemm(x, Wq, tmp, M1, C_, C_);
    run_stats(tmp, M1, C_, 16);
    bn_leaky_kernel<<<(int)((tot1 + BLK - 1) / BLK), BLK>>>(tmp, gq, bq, q, C_, tot1);

    run_gemm(x, Wk, tmp, M1, C_, C_);
    run_stats(tmp, M1, C_, 16);
    bn_leaky_kernel<<<(int)((tot1 + BLK - 1) / BLK), BLK>>>(tmp, gk, bk, k, C_, tot1);

    run_gemm(x, Wv, tmp, M1, C_, C_);
    run_stats(tmp, M1, C_, 16);
    bn_leaky_kernel<<<(int)((tot1 + BLK - 1) / BLK), BLK>>>(tmp, gv, bv, v, C_, tot1);

    // ---- kNN: sq, dist, topk ----
    sq_kernel<<<(M1 * 32 + BLK - 1) / BLK, BLK>>>(k, sqb);
    {
        dim3 grid(NPTS / 64, NPTS / 64, B_);
        dist_kernel<<<grid, 256>>>(k, sqb, dist);
    }
    topk_kernel<<<M1, 256>>>(dist);

    // ---- masked_pos gather + posb conv2 ----
    mpos_kernel<<<(int)((totB + BLK - 1) / BLK), BLK>>>(pos);
    run_gemm(big0, Wpb, big1, M2, C_, C_);
    run_stats(big1, M2, C_, 64);
    posb_combine_kernel<<<(int)((totB + BLK - 1) / BLK), BLK>>>(gpb, bpb);

    // ---- vector = conv2(conv2(vecin, We1), We2) ----
    run_gemm(big0, We1, s1, M2, CPH, C_);
    run_stats(s1, M2, CPH, 64);
    bn_leaky_kernel<<<(int)((totS + BLK - 1) / BLK), BLK>>>(s1, ge1, be1, s1, CPH, totS);

    run_gemm(s1, We2, s2, M2, CPH, CPH);
    run_stats(s2, M2, CPH, 64);
    bn_leaky_kernel<<<(int)((totS + BLK - 1) / BLK), BLK>>>(s2, ge2, be2, s2, CPH, totS);

    // ---- softmax over k, attention, residual ----
    attn_kernel<<<M1, 256>>>(x, xatt);

    // ---- MLP: h = silu(bn(xattn @ Wm1^T)); m = silu(bn(h @ Wm2^T)); out = xattn + m ----
    run_gemm(xatt, Wm1, tmp, M1, HID, C_);
    run_stats(tmp, M1, HID, 16);
    {
        size_t t2 = (size_t)M1 * HID;
        bn_silu_kernel<<<(int)((t2 + BLK - 1) / BLK), BLK>>>(tmp, gm1, bm1, hbuf, HID, t2);
    }

    run_gemm(hbuf, Wm2, tmp, M1, C_, HID);
    run_stats(tmp, M1, C_, 16);
    bn_silu_res_kernel<<<(int)((tot1 + BLK - 1) / BLK), BLK>>>(tmp, gm2, bm2, xatt, out, C_, tot1);
}

// round 4
// speedup vs baseline: 1.9420x; 1.9420x over previous
#include <cuda_runtime.h>
#include <math.h>
#include <float.h>

#define B_   2
#define NPTS 2048
#define C_   256
#define KNB  32
#define HID  512
#define CPH  32
#define M1   (B_*NPTS)        // 4096
#define M2   (B_*NPTS*KNB)    // 131072
#define EPSB 1e-5f

// stage ids for folded BN coefficients
#define ST_Q  0
#define ST_K  1
#define ST_V  2
#define ST_PB 3
#define ST_S1 4
#define ST_S2 5
#define ST_M1 6
#define ST_M2 7

// ---------------- device scratch ----------------
__device__ float g_qb[M1*C_];
__device__ float g_kb[M1*C_];
__device__ float g_vb[M1*C_];
__device__ float g_tmp4[(size_t)M1*C_*4];      // raw q,k,v + P (slice 3), reused for MLP raw
__device__ float g_sqv[M1];
__device__ float g_dist[(size_t)B_*NPTS*NPTS];
__device__ int   g_idx[M2];
__device__ float g_s1[(size_t)M2*CPH];
__device__ float g_s2[(size_t)M2*CPH];
__device__ float g_xattn[M1*C_];
__device__ float g_hb[M1*HID];
__device__ double g_dsum[HID];
__device__ double g_dsum2[HID];
__device__ float g_afa[8][HID];
__device__ float g_afc[8][HID];

__device__ __forceinline__ float lrelu(float z) { return z >= 0.f ? z : 0.2f * z; }

// ---------------- batched TN GEMM: C[m,n] = sum_k A[m,k]*W[n,k] ----------------
// BM=BN=128, BK=16, 256 threads, 8x8 per thread. M%128==0, N%128==0, K%16==0.
struct Gemm4 {
    const float* A[4];
    const float* W[4];
    float*       C[4];
};

__global__ __launch_bounds__(256)
void gemm128_kernel(Gemm4 g, int M, int N, int K)
{
    __shared__ float As[16][128];
    __shared__ float Ws[16][128];
    const float* A = g.A[blockIdx.z];
    const float* W = g.W[blockIdx.z];
    float*       C = g.C[blockIdx.z];
    int tid = threadIdx.x;
    int tx = tid & 15, ty = tid >> 4;
    int m0 = blockIdx.y * 128, n0 = blockIdx.x * 128;
    int lr = tid >> 2;
    int lc = (tid & 3) << 2;
    float acc[8][8] = {};

    for (int k0 = 0; k0 < K; k0 += 16) {
        float4 a0 = *(const float4*)&A[(size_t)(m0 + lr)      * K + k0 + lc];
        float4 a1 = *(const float4*)&A[(size_t)(m0 + lr + 64) * K + k0 + lc];
        float4 w0 = *(const float4*)&W[(size_t)(n0 + lr)      * K + k0 + lc];
        float4 w1 = *(const float4*)&W[(size_t)(n0 + lr + 64) * K + k0 + lc];
        As[lc+0][lr] = a0.x; As[lc+1][lr] = a0.y; As[lc+2][lr] = a0.z; As[lc+3][lr] = a0.w;
        As[lc+0][lr+64] = a1.x; As[lc+1][lr+64] = a1.y; As[lc+2][lr+64] = a1.z; As[lc+3][lr+64] = a1.w;
        Ws[lc+0][lr] = w0.x; Ws[lc+1][lr] = w0.y; Ws[lc+2][lr] = w0.z; Ws[lc+3][lr] = w0.w;
        Ws[lc+0][lr+64] = w1.x; Ws[lc+1][lr+64] = w1.y; Ws[lc+2][lr+64] = w1.z; Ws[lc+3][lr+64] = w1.w;
        __syncthreads();
        #pragma unroll
        for (int kk = 0; kk < 16; kk++) {
            float a[8], b[8];
            *(float4*)(a)     = *(const float4*)&As[kk][ty*8];
            *(float4*)(a + 4) = *(const float4*)&As[kk][ty*8 + 4];
            *(float4*)(b)     = *(const float4*)&Ws[kk][tx*8];
            *(float4*)(b + 4) = *(const float4*)&Ws[kk][tx*8 + 4];
            #pragma unroll
            for (int i = 0; i < 8; i++)
                #pragma unroll
                for (int j = 0; j < 8; j++)
                    acc[i][j] += a[i] * b[j];
        }
        __syncthreads();
    }
    #pragma unroll
    for (int i = 0; i < 8; i++) {
        size_t row = (size_t)(m0 + ty*8 + i) * N + n0 + tx*8;
        *(float4*)&C[row]     = make_float4(acc[i][0], acc[i][1], acc[i][2], acc[i][3]);
        *(float4*)&C[row + 4] = make_float4(acc[i][4], acc[i][5], acc[i][6], acc[i][7]);
    }
}

// ---------------- dist = sq[m]+sq[n]-2*k_m.k_n, per batch ----------------
__global__ __launch_bounds__(256)
void dist_kernel(const float* __restrict__ key, const float* __restrict__ sq,
                 float* __restrict__ dist)
{
    int b = blockIdx.z;
    const float* A  = key + (size_t)b * NPTS * C_;
    const float* sb = sq + b * NPTS;
    float* D = dist + (size_t)b * NPTS * NPTS;

    __shared__ float As[16][128];
    __shared__ float Ws[16][128];
    int tid = threadIdx.x;
    int tx = tid & 15, ty = tid >> 4;
    int m0 = blockIdx.y * 128, n0 = blockIdx.x * 128;
    int lr = tid >> 2;
    int lc = (tid & 3) << 2;
    float acc[8][8] = {};

    for (int k0 = 0; k0 < C_; k0 += 16) {
        float4 a0 = *(const float4*)&A[(size_t)(m0 + lr)      * C_ + k0 + lc];
        float4 a1 = *(const float4*)&A[(size_t)(m0 + lr + 64) * C_ + k0 + lc];
        float4 w0 = *(const float4*)&A[(size_t)(n0 + lr)      * C_ + k0 + lc];
        float4 w1 = *(const float4*)&A[(size_t)(n0 + lr + 64) * C_ + k0 + lc];
        As[lc+0][lr] = a0.x; As[lc+1][lr] = a0.y; As[lc+2][lr] = a0.z; As[lc+3][lr] = a0.w;
        As[lc+0][lr+64] = a1.x; As[lc+1][lr+64] = a1.y; As[lc+2][lr+64] = a1.z; As[lc+3][lr+64] = a1.w;
        Ws[lc+0][lr] = w0.x; Ws[lc+1][lr] = w0.y; Ws[lc+2][lr] = w0.z; Ws[lc+3][lr] = w0.w;
        Ws[lc+0][lr+64] = w1.x; Ws[lc+1][lr+64] = w1.y; Ws[lc+2][lr+64] = w1.z; Ws[lc+3][lr+64] = w1.w;
        __syncthreads();
        #pragma unroll
        for (int kk = 0; kk < 16; kk++) {
            float a[8], b[8];
            *(float4*)(a)     = *(const float4*)&As[kk][ty*8];
            *(float4*)(a + 4) = *(const float4*)&As[kk][ty*8 + 4];
            *(float4*)(b)     = *(const float4*)&Ws[kk][tx*8];
            *(float4*)(b + 4) = *(const float4*)&Ws[kk][tx*8 + 4];
            #pragma unroll
            for (int i = 0; i < 8; i++)
                #pragma unroll
                for (int j = 0; j < 8; j++)
                    acc[i][j] += a[i] * b[j];
        }
        __syncthreads();
    }
    #pragma unroll
    for (int i = 0; i < 8; i++) {
        int gm = m0 + ty*8 + i;
        float sm = sb[gm];
        #pragma unroll
        for (int j = 0; j < 8; j++) {
            int gn = n0 + tx*8 + j;
            D[(size_t)gm * NPTS + gn] = sm + sb[gn] - 2.f * acc[i][j];
        }
    }
}

// ---------------- sq[row] = sum_d key[row,d]^2 ----------------
__global__ void sq_kernel(const float* __restrict__ key, float* __restrict__ sq)
{
    int w = (blockIdx.x * blockDim.x + threadIdx.x) >> 5;
    int lane = threadIdx.x & 31;
    if (w < M1) {
        const float* p = key + (size_t)w * C_;
        float s = 0.f;
        for (int d = lane; d < C_; d += 32) { float v = p[d]; s += v * v; }
        #pragma unroll
        for (int o = 16; o; o >>= 1) s += __shfl_down_sync(0xffffffffu, s, o);
        if (lane == 0) sq[w] = s;
    }
}

// ---------------- top-32 smallest per row ----------------
__global__ __launch_bounds__(256)
void topk_kernel(const float* __restrict__ dist)
{
    int bn = blockIdx.x;
    const float* row = dist + (size_t)bn * NPTS;
    __shared__ float sv[NPTS];
    __shared__ float rv[256];
    __shared__ int   ri[256];
    int t = threadIdx.x;
    for (int j = t; j < NPTS; j += 256) sv[j] = row[j];
    __syncthreads();

    for (int sel = 0; sel < KNB; sel++) {
        float best = FLT_MAX; int bi = 1 << 30;
        for (int j = t; j < NPTS; j += 256) {
            float v = sv[j];
            if (v < best || (v == best && j < bi)) { best = v; bi = j; }
        }
        rv[t] = best; ri[t] = bi;
        __syncthreads();
        for (int s = 128; s > 0; s >>= 1) {
            if (t < s) {
                if (rv[t + s] < rv[t] || (rv[t + s] == rv[t] && ri[t + s] < ri[t])) {
                    rv[t] = rv[t + s]; ri[t] = ri[t + s];
                }
            }
            __syncthreads();
        }
        if (t == 0) {
            g_idx[(size_t)bn * KNB + sel] = ri[0];
            sv[ri[0]] = FLT_MAX;
        }
        __syncthreads();
    }
}

// ---------------- per-channel batch stats ----------------
__global__ void zero_stats_kernel(int D)
{
    int i = blockIdx.x * blockDim.x + threadIdx.x;
    if (i < D) { g_dsum[i] = 0.0; g_dsum2[i] = 0.0; }
}

__global__ void stats_partial_kernel(const float* __restrict__ Y, int M, int D)
{
    int d = blockIdx.x * 32 + threadIdx.x;
    int stride = gridDim.y * blockDim.y;
    float s = 0.f, s2 = 0.f;
    if (d < D) {
        for (int i = blockIdx.y * blockDim.y + threadIdx.y; i < M; i += stride) {
            float v = Y[(size_t)i * D + d];
            s += v; s2 += v * v;
        }
    }
    __shared__ float sh[8][32], sh2[8][32];
    sh[threadIdx.y][threadIdx.x]  = s;
    sh2[threadIdx.y][threadIdx.x] = s2;
    __syncthreads();
    if (threadIdx.y == 0 && d < D) {
        double ts = 0.0, ts2 = 0.0;
        #pragma unroll
        for (int r = 0; r < 8; r++) { ts += sh[r][threadIdx.x]; ts2 += sh2[r][threadIdx.x]; }
        atomicAdd(&g_dsum[d], ts);
        atomicAdd(&g_dsum2[d], ts2);
    }
}

// fold BN: a = gamma/sqrt(var+eps); c = beta - mean*a
__global__ void stats_finalize_fold(const float* __restrict__ gamma, const float* __restrict__ beta,
                                    int M, int D, int stage)
{
    int d = blockIdx.x * blockDim.x + threadIdx.x;
    if (d < D) {
        double m = g_dsum[d] / (double)M;
        double v = g_dsum2[d] / (double)M - m * m;
        if (v < 0.0) v = 0.0;
        float a = gamma[d] * rsqrtf((float)v + EPSB);
        g_afa[stage][d] = a;
        g_afc[stage][d] = beta[d] - (float)m * a;
    }
}

// ---------------- posb_raw stats: val = P[jg,d] - P[bn,d] over all (bn,k) ----------------
__global__ __launch_bounds__(256)
void pbstats_kernel(const float* __restrict__ P)
{
    int d = threadIdx.x;             // 256 channels
    int rows = M2 / gridDim.x;
    int r0 = blockIdx.x * rows;
    float s = 0.f, s2 = 0.f;
    for (int r = r0; r < r0 + rows; r++) {
        int bn = r >> 5;
        int b  = r >> 16;            // NPTS*KNB = 65536
        int jg = (b << 11) + g_idx[r];
        float val = P[(size_t)jg * C_ + d] - P[(size_t)bn * C_ + d];
        s += val; s2 += val * val;
    }
    atomicAdd(&g_dsum[d],  (double)s);
    atomicAdd(&g_dsum2[d], (double)s2);
}

// ---------------- BN apply kernels (folded) ----------------
__global__ void bn_leaky_apply(const float* __restrict__ Y, float* __restrict__ out,
                               int D, size_t total, int stage)
{
    size_t e = (size_t)blockIdx.x * blockDim.x + threadIdx.x;
    if (e < total) {
        int d = (int)(e % D);
        float z = g_afa[stage][d] * Y[e] + g_afc[stage][d];
        out[e] = z >= 0.f ? z : 0.2f * z;
    }
}

__global__ void bn_silu_apply(const float* __restrict__ Y, float* __restrict__ out,
                              int D, size_t total, int stage)
{
    size_t e = (size_t)blockIdx.x * blockDim.x + threadIdx.x;
    if (e < total) {
        int d = (int)(e % D);
        float z = g_afa[stage][d] * Y[e] + g_afc[stage][d];
        out[e] = z / (1.f + expf(-z));
    }
}

__global__ void bn_silu_res_apply(const float* __restrict__ Y, const float* __restrict__ res,
                                  float* __restrict__ out, int D, size_t total, int stage)
{
    size_t e = (size_t)blockIdx.x * blockDim.x + threadIdx.x;
    if (e < total) {
        int d = (int)(e % D);
        float z = g_afa[stage][d] * Y[e] + g_afc[stage][d];
        out[e] = res[e] + z / (1.f + expf(-z));
    }
}

// ---------------- vec1: s1_raw[r,g] = sum_d vecin[r,d]*We1[g,d], vecin fused gather ----------------
// BM=128 rows (4 consecutive bn), BN=32, BK=16, 256 threads, 8x2 per thread.
__global__ __launch_bounds__(256)
void vec1_kernel(const float* __restrict__ qb, const float* __restrict__ kb,
                 const float* __restrict__ P,  const float* __restrict__ We1,
                 float* __restrict__ s1)
{
    __shared__ float As[16][128];
    __shared__ float Ws[16][32];
    __shared__ int sj[128];
    int tid = threadIdx.x;
    int m0 = blockIdx.x * 128;
    if (tid < 128) sj[tid] = g_idx[m0 + tid];
    __syncthreads();

    int tx = tid & 15, ty = tid >> 4;
    int lr = tid >> 2;
    int lc = (tid & 3) << 2;
    int r0 = m0 + lr,      bn0 = r0 >> 5, b0 = r0 >> 16;
    int r1 = m0 + lr + 64, bn1 = r1 >> 5, b1 = r1 >> 16;
    int jg0 = (b0 << 11) + sj[lr];
    int jg1 = (b1 << 11) + sj[lr + 64];
    float acc[8][2] = {};

    for (int k0 = 0; k0 < C_; k0 += 16) {
        #pragma unroll
        for (int h = 0; h < 2; h++) {
            int jg = h ? jg1 : jg0;
            int bn = h ? bn1 : bn0;
            int rr = h ? lr + 64 : lr;
            float4 kf = *(const float4*)&kb[(size_t)jg * C_ + k0 + lc];
            float4 qf = *(const float4*)&qb[(size_t)bn * C_ + k0 + lc];
            float4 pj = *(const float4*)&P [(size_t)jg * C_ + k0 + lc];
            float4 pn = *(const float4*)&P [(size_t)bn * C_ + k0 + lc];
            float4 pa = *(const float4*)&g_afa[ST_PB][k0 + lc];
            float4 pc = *(const float4*)&g_afc[ST_PB][k0 + lc];
            As[lc+0][rr] = kf.x - qf.x + lrelu(pa.x * (pj.x - pn.x) + pc.x);
            As[lc+1][rr] = kf.y - qf.y + lrelu(pa.y * (pj.y - pn.y) + pc.y);
            As[lc+2][rr] = kf.z - qf.z + lrelu(pa.z * (pj.z - pn.z) + pc.z);
            As[lc+3][rr] = kf.w - qf.w + lrelu(pa.w * (pj.w - pn.w) + pc.w);
        }
        {
            int i0 = tid;           // 512 elems: g = i&31, kk = i>>5
            Ws[i0 >> 5][i0 & 31] = We1[(size_t)(i0 & 31) * C_ + k0 + (i0 >> 5)];
            int i1 = tid + 256;
            Ws[i1 >> 5][i1 & 31] = We1[(size_t)(i1 & 31) * C_ + k0 + (i1 >> 5)];
        }
        __syncthreads();
        #pragma unroll
        for (int kk = 0; kk < 16; kk++) {
            float a[8];
            *(float4*)(a)     = *(const float4*)&As[kk][ty*8];
            *(float4*)(a + 4) = *(const float4*)&As[kk][ty*8 + 4];
            float b0v = Ws[kk][tx*2], b1v = Ws[kk][tx*2 + 1];
            #pragma unroll
            for (int i = 0; i < 8; i++) {
                acc[i][0] += a[i] * b0v;
                acc[i][1] += a[i] * b1v;
            }
        }
        __syncthreads();
    }
    #pragma unroll
    for (int i = 0; i < 8; i++) {
        size_t row = (size_t)(m0 + ty*8 + i) * CPH + tx*2;
        s1[row]     = acc[i][0];
        s1[row + 1] = acc[i][1];
    }
}

// ---------------- vec2: s2_raw = leaky(bn(s1_raw)) @ We2^T, BN fused in A load ----------------
__global__ __launch_bounds__(256)
void vec2_kernel(const float* __restrict__ s1, const float* __restrict__ We2,
                 float* __restrict__ s2)
{
    __shared__ float As[16][128];
    __shared__ float Ws[16][32];
    int tid = threadIdx.x;
    int m0 = blockIdx.x * 128;
    int tx = tid & 15, ty = tid >> 4;
    int lr = tid >> 2;
    int lc = (tid & 3) << 2;
    float acc[8][2] = {};

    for (int k0 = 0; k0 < CPH; k0 += 16) {
        #pragma unroll
        for (int h = 0; h < 2; h++) {
            int rr = h ? lr + 64 : lr;
            float4 y  = *(const float4*)&s1[(size_t)(m0 + rr) * CPH + k0 + lc];
            float4 aa = *(const float4*)&g_afa[ST_S1][k0 + lc];
            float4 cc = *(const float4*)&g_afc[ST_S1][k0 + lc];
            As[lc+0][rr] = lrelu(aa.x * y.x + cc.x);
            As[lc+1][rr] = lrelu(aa.y * y.y + cc.y);
            As[lc+2][rr] = lrelu(aa.z * y.z + cc.z);
            As[lc+3][rr] = lrelu(aa.w * y.w + cc.w);
        }
        {
            int i0 = tid;
            Ws[i0 >> 5][i0 & 31] = We2[(size_t)(i0 & 31) * CPH + k0 + (i0 >> 5)];
            int i1 = tid + 256;
            Ws[i1 >> 5][i1 & 31] = We2[(size_t)(i1 & 31) * CPH + k0 + (i1 >> 5)];
        }
        __syncthreads();
        #pragma unroll
        for (int kk = 0; kk < 16; kk++) {
            float a[8];
            *(float4*)(a)     = *(const float4*)&As[kk][ty*8];
            *(float4*)(a + 4) = *(const float4*)&As[kk][ty*8 + 4];
            float b0v = Ws[kk][tx*2], b1v = Ws[kk][tx*2 + 1];
            #pragma unroll
            for (int i = 0; i < 8; i++) {
                acc[i][0] += a[i] * b0v;
                acc[i][1] += a[i] * b1v;
            }
        }
        __syncthreads();
    }
    #pragma unroll
    for (int i = 0; i < 8; i++) {
        size_t row = (size_t)(m0 + ty*8 + i) * CPH + tx*2;
        s2[row]     = acc[i][0];
        s2[row + 1] = acc[i][1];
    }
}

// ---------------- attention: BN+leaky(s2) -> softmax over k -> combine value, + residual ----------------
__global__ __launch_bounds__(256)
void attn_kernel(const float* __restrict__ x, const float* __restrict__ s2,
                 const float* __restrict__ vb, const float* __restrict__ P,
                 float* __restrict__ xattn)
{
    int bn = blockIdx.x;
    int t = threadIdx.x;
    __shared__ float soft[KNB][CPH + 1];
    __shared__ int sj[KNB];
    size_t base = (size_t)bn * KNB * CPH;
    for (int e = t; e < KNB * CPH; e += 256) {
        int g = e & 31;
        float y = s2[base + e];
        soft[e >> 5][g] = lrelu(g_afa[ST_S2][g] * y + g_afc[ST_S2][g]);
    }
    if (t < KNB) sj[t] = g_idx[(size_t)bn * KNB + t];
    __syncthreads();
    if (t < CPH) {
        float mx = -FLT_MAX;
        #pragma unroll
        for (int k = 0; k < KNB; k++) mx = fmaxf(mx, soft[k][t]);
        float s = 0.f;
        #pragma unroll
        for (int k = 0; k < KNB; k++) { float ev = expf(soft[k][t] - mx); soft[k][t] = ev; s += ev; }
        float inv = 1.f / s;
        #pragma unroll
        for (int k = 0; k < KNB; k++) soft[k][t] *= inv;
    }
    __syncthreads();

    int c = t, g = t >> 3;
    int b = bn >> 11;
    float pn = P[(size_t)bn * C_ + c];
    float pa = g_afa[ST_PB][c], pc = g_afc[ST_PB][c];
    float acc = 0.f;
    #pragma unroll
    for (int k = 0; k < KNB; k++) {
        int jg = (b << 11) + sj[k];
        float posb = lrelu(pa * (P[(size_t)jg * C_ + c] - pn) + pc);
        acc += (vb[(size_t)jg * C_ + c] + posb) * soft[k][g];
    }
    size_t o = (size_t)bn * C_ + c;
    xattn[o] = x[o] + acc;
}

// ---------------- host helpers ----------------
static inline void run_stats_fold(const float* Y, int M, int D, int splits,
                                  const float* gamma, const float* beta, int stage)
{
    zero_stats_kernel<<<(D + 255) / 256, 256>>>(D);
    dim3 grid((D + 31) / 32, splits);
    dim3 blk(32, 8);
    stats_partial_kernel<<<grid, blk>>>(Y, M, D);
    stats_finalize_fold<<<(D + 255) / 256, 256>>>(gamma, beta, M, D, stage);
}

extern "C" void kernel_launch(void* const* d_in, const int* in_sizes, int n_in,
                              void* d_out, int out_size)
{
    const float* x   = (const float*)d_in[0];
    const float* pos = (const float*)d_in[1];
    const float* Wq  = (const float*)d_in[2];
    const float* gq  = (const float*)d_in[3];
    const float* bq  = (const float*)d_in[4];
    const float* Wk  = (const float*)d_in[5];
    const float* gk  = (const float*)d_in[6];
    const float* bk  = (const float*)d_in[7];
    const float* Wv  = (const float*)d_in[8];
    const float* gv  = (const float*)d_in[9];
    const float* bv  = (const float*)d_in[10];
    const float* Wpb = (const float*)d_in[11];
    const float* gpb = (const float*)d_in[12];
    const float* bpb = (const float*)d_in[13];
    const float* We1 = (const float*)d_in[14];
    const float* ge1 = (const float*)d_in[15];
    const float* be1 = (const float*)d_in[16];
    const float* We2 = (const float*)d_in[17];
    const float* ge2 = (const float*)d_in[18];
    const float* be2 = (const float*)d_in[19];
    const float* Wm1 = (const float*)d_in[20];
    const float* gm1 = (const float*)d_in[21];
    const float* bm1 = (const float*)d_in[22];
    const float* Wm2 = (const float*)d_in[23];
    const float* gm2 = (const float*)d_in[24];
    const float* bm2 = (const float*)d_in[25];
    float* out = (float*)d_out;

    void* p;
    float *qb, *kb, *vb, *tmp, *sqv, *dist, *s1, *s2, *xatt, *hb;
    cudaGetSymbolAddress(&p, g_qb);    qb   = (float*)p;
    cudaGetSymbolAddress(&p, g_kb);    kb   = (float*)p;
    cudaGetSymbolAddress(&p, g_vb);    vb   = (float*)p;
    cudaGetSymbolAddress(&p, g_tmp4);  tmp  = (float*)p;
    cudaGetSymbolAddress(&p, g_sqv);   sqv  = (float*)p;
    cudaGetSymbolAddress(&p, g_dist);  dist = (float*)p;
    cudaGetSymbolAddress(&p, g_s1);    s1   = (float*)p;
    cudaGetSymbolAddress(&p, g_s2);    s2   = (float*)p;
    cudaGetSymbolAddress(&p, g_xattn); xatt = (float*)p;
    cudaGetSymbolAddress(&p, g_hb);    hb   = (float*)p;

    const size_t SL = (size_t)M1 * C_;       // one tmp slice (4096*256)
    float* t0 = tmp;          // raw q   -> later MLP1 raw (slices 0-1)
    float* t1 = tmp + SL;     // raw k
    float* t2 = tmp + 2*SL;   // raw v   -> later MLP2 raw
    float* t3 = tmp + 3*SL;   // P = pos @ Wpb^T  (no BN!)

    const size_t tot1 = SL;
    const int BLK = 256;

    // ---- 1. batched GEMM: q,k,v raw + P ----
    {
        Gemm4 g = { { x, x, x, pos }, { Wq, Wk, Wv, Wpb }, { t0, t1, t2, t3 } };
        gemm128_kernel<<<dim3(C_/128, M1/128, 4), 256>>>(g, M1, C_, C_);
    }
    run_stats_fold(t0, M1, C_, 16, gq, bq, ST_Q);
    bn_leaky_apply<<<(int)((tot1 + BLK - 1) / BLK), BLK>>>(t0, qb, C_, tot1, ST_Q);
    run_stats_fold(t1, M1, C_, 16, gk, bk, ST_K);
    bn_leaky_apply<<<(int)((tot1 + BLK - 1) / BLK), BLK>>>(t1, kb, C_, tot1, ST_K);
    run_stats_fold(t2, M1, C_, 16, gv, bv, ST_V);
    bn_leaky_apply<<<(int)((tot1 + BLK - 1) / BLK), BLK>>>(t2, vb, C_, tot1, ST_V);

    // ---- 2. kNN ----
    sq_kernel<<<(M1 * 32 + BLK - 1) / BLK, BLK>>>(kb, sqv);
    dist_kernel<<<dim3(NPTS/128, NPTS/128, B_), 256>>>(kb, sqv, dist);
    topk_kernel<<<M1, 256>>>(dist);

    // ---- 3. posb stats (unmaterialized P[j]-P[n]) ----
    zero_stats_kernel<<<(C_ + 255) / 256, 256>>>(C_);
    pbstats_kernel<<<128, 256>>>(t3);
    stats_finalize_fold<<<(C_ + 255) / 256, 256>>>(gpb, bpb, M2, C_, ST_PB);

    // ---- 4. vector path ----
    vec1_kernel<<<M2/128, 256>>>(qb, kb, t3, We1, s1);
    run_stats_fold(s1, M2, CPH, 64, ge1, be1, ST_S1);
    vec2_kernel<<<M2/128, 256>>>(s1, We2, s2);
    run_stats_fold(s2, M2, CPH, 64, ge2, be2, ST_S2);

    // ---- 5. attention + residual ----
    attn_kernel<<<M1, 256>>>(x, s2, vb, t3, xatt);

    // ---- 6. MLP ----
    {
        Gemm4 g = { { xatt, xatt, xatt, xatt }, { Wm1, Wm1, Wm1, Wm1 }, { t0, t0, t0, t0 } };
        gemm128_kernel<<<dim3(HID/128, M1/128, 1), 256>>>(g, M1, HID, C_);
    }
    run_stats_fold(t0, M1, HID, 16, gm1, bm1, ST_M1);
    {
        size_t th = (size_t)M1 * HID;
        bn_silu_apply<<<(int)((th + BLK - 1) / BLK), BLK>>>(t0, hb, HID, th, ST_M1);
    }
    {
        Gemm4 g = { { hb, hb, hb, hb }, { Wm2, Wm2, Wm2, Wm2 }, { t2, t2, t2, t2 } };
        gemm128_kernel<<<dim3(C_/128, M1/128, 1), 256>>>(g, M1, C_, HID);
    }
    run_stats_fold(t2, M1, C_, 16, gm2, bm2, ST_M2);
    bn_silu_res_apply<<<(int)((tot1 + BLK - 1) / BLK), BLK>>>(t2, xatt, out, C_, tot1, ST_M2);
}

// round 5
// speedup vs baseline: 1.9742x; 1.0166x over previous
#include <cuda_runtime.h>
#include <math.h>
#include <float.h>

#define B_   2
#define NPTS 2048
#define C_   256
#define KNB  32
#define HID  512
#define CPH  32
#define M1   (B_*NPTS)        // 4096
#define M2   (B_*NPTS*KNB)    // 131072
#define EPSB 1e-5f

#define ST_Q  0
#define ST_K  1
#define ST_V  2
#define ST_PB 3
#define ST_S1 4
#define ST_S2 5
#define ST_M1 6
#define ST_M2 7

typedef unsigned long long ull;

// ---------------- device scratch ----------------
__device__ float g_qkv[3*M1*C_];               // q, k, v (BN applied)
__device__ float g_tmp4[(size_t)M1*C_*4];      // raw q,k,v + P; reused for MLP raws
__device__ float g_sqv[M1];
__device__ float g_dist[(size_t)B_*NPTS*NPTS];
__device__ int   g_idx[M2];
__device__ float g_s1[(size_t)M2*CPH];
__device__ float g_s2[(size_t)M2*CPH];
__device__ float g_xattn[M1*C_];
__device__ double g_dsum[8][HID];
__device__ double g_dsum2[8][HID];
__device__ float g_afa[8][HID];
__device__ float g_afc[8][HID];

__device__ __forceinline__ float lrelu(float z) { return z >= 0.f ? z : 0.2f * z; }

// ---------------- packed f32x2 helpers ----------------
__device__ __forceinline__ void fma2(ull& d, ull a, ull b) {
    asm("fma.rn.f32x2 %0, %1, %2, %0;" : "+l"(d) : "l"(a), "l"(b));
}
__device__ __forceinline__ ull add2(ull a, ull b) {
    ull d; asm("add.rn.f32x2 %0, %1, %2;" : "=l"(d) : "l"(a), "l"(b)); return d;
}
__device__ __forceinline__ ull mul2(ull a, ull b) {
    ull d; asm("mul.rn.f32x2 %0, %1, %2;" : "=l"(d) : "l"(a), "l"(b)); return d;
}
__device__ __forceinline__ ull dup2(float x) {
    ull r; asm("mov.b64 %0, {%1, %1};" : "=l"(r) : "f"(x)); return r;
}
__device__ __forceinline__ float2 unpk(ull v) {
    float2 f; asm("mov.b64 {%0, %1}, %2;" : "=f"(f.x), "=f"(f.y) : "l"(v)); return f;
}

// ---------------- batched TN GEMM, FMA2, fused stats, optional silu-A ----------------
// C[m,n] = sum_k T(A[m,k]) * W[n,k].  BM=BN=128, BK=16, 256 thr, 8x8/thread.
struct Gemm4 {
    const float* A[4];
    const float* W[4];
    float*       C[4];
    int          stage[4];   // -1 = no stats
};

__global__ __launch_bounds__(256)
void gemm128_kernel(Gemm4 g, int N, int K, int dosilu)
{
    __shared__ __align__(16) float As[16][128];
    __shared__ __align__(16) float Wd[16][256];
    int z = blockIdx.z;
    const float* A = g.A[z];
    const float* W = g.W[z];
    float*       C = g.C[z];
    int stage = g.stage[z];
    int tid = threadIdx.x;
    int tx = tid & 15, ty = tid >> 4;
    int m0 = blockIdx.y * 128, n0 = blockIdx.x * 128;
    int lr = tid >> 2;
    int lc = (tid & 3) << 2;
    ull acc[4][8] = {};

    for (int k0 = 0; k0 < K; k0 += 16) {
        float4 a0 = *(const float4*)&A[(size_t)(m0 + lr)      * K + k0 + lc];
        float4 a1 = *(const float4*)&A[(size_t)(m0 + lr + 64) * K + k0 + lc];
        if (dosilu) {
            #pragma unroll
            for (int i = 0; i < 4; i++) {
                float aa = g_afa[ST_M1][k0 + lc + i];
                float cc = g_afc[ST_M1][k0 + lc + i];
                float* pz = (i==0)?&a0.x:(i==1)?&a0.y:(i==2)?&a0.z:&a0.w;
                float* pw = (i==0)?&a1.x:(i==1)?&a1.y:(i==2)?&a1.z:&a1.w;
                float z0 = aa * (*pz) + cc; *pz = z0 / (1.f + __expf(-z0));
                float z1 = aa * (*pw) + cc; *pw = z1 / (1.f + __expf(-z1));
            }
        }
        float4 w0 = *(const float4*)&W[(size_t)(n0 + lr)      * K + k0 + lc];
        float4 w1 = *(const float4*)&W[(size_t)(n0 + lr + 64) * K + k0 + lc];
        As[lc+0][lr] = a0.x; As[lc+1][lr] = a0.y; As[lc+2][lr] = a0.z; As[lc+3][lr] = a0.w;
        As[lc+0][lr+64] = a1.x; As[lc+1][lr+64] = a1.y; As[lc+2][lr+64] = a1.z; As[lc+3][lr+64] = a1.w;
        *(ull*)&Wd[lc+0][2*lr] = dup2(w0.x);
        *(ull*)&Wd[lc+1][2*lr] = dup2(w0.y);
        *(ull*)&Wd[lc+2][2*lr] = dup2(w0.z);
        *(ull*)&Wd[lc+3][2*lr] = dup2(w0.w);
        *(ull*)&Wd[lc+0][2*(lr+64)] = dup2(w1.x);
        *(ull*)&Wd[lc+1][2*(lr+64)] = dup2(w1.y);
        *(ull*)&Wd[lc+2][2*(lr+64)] = dup2(w1.z);
        *(ull*)&Wd[lc+3][2*(lr+64)] = dup2(w1.w);
        __syncthreads();
        #pragma unroll
        for (int kk = 0; kk < 16; kk++) {
            ulonglong2 aA = *(const ulonglong2*)&As[kk][ty*8];
            ulonglong2 aB = *(const ulonglong2*)&As[kk][ty*8 + 4];
            ull ap[4] = { aA.x, aA.y, aB.x, aB.y };
            ulonglong2 v0 = *(const ulonglong2*)&Wd[kk][16*tx];
            ulonglong2 v1 = *(const ulonglong2*)&Wd[kk][16*tx + 4];
            ulonglong2 v2 = *(const ulonglong2*)&Wd[kk][16*tx + 8];
            ulonglong2 v3 = *(const ulonglong2*)&Wd[kk][16*tx + 12];
            ull wp[8] = { v0.x, v0.y, v1.x, v1.y, v2.x, v2.y, v3.x, v3.y };
            #pragma unroll
            for (int i2 = 0; i2 < 4; i2++)
                #pragma unroll
                for (int j = 0; j < 8; j++)
                    fma2(acc[i2][j], ap[i2], wp[j]);
        }
        __syncthreads();
    }

    // store C
    #pragma unroll
    for (int i2 = 0; i2 < 4; i2++) {
        float2 p[8];
        #pragma unroll
        for (int j = 0; j < 8; j++) p[j] = unpk(acc[i2][j]);
        size_t r0 = (size_t)(m0 + ty*8 + 2*i2) * N + n0 + tx*8;
        size_t r1 = r0 + N;
        *(float4*)&C[r0]     = make_float4(p[0].x, p[1].x, p[2].x, p[3].x);
        *(float4*)&C[r0 + 4] = make_float4(p[4].x, p[5].x, p[6].x, p[7].x);
        *(float4*)&C[r1]     = make_float4(p[0].y, p[1].y, p[2].y, p[3].y);
        *(float4*)&C[r1 + 4] = make_float4(p[4].y, p[5].y, p[6].y, p[7].y);
    }

    // fused stats: column sums/sumsq over the 128 rows of this block
    if (stage >= 0) {
        float ps[8], ps2[8];
        #pragma unroll
        for (int j = 0; j < 8; j++) {
            ull s = add2(add2(acc[0][j], acc[1][j]), add2(acc[2][j], acc[3][j]));
            ull q = add2(add2(mul2(acc[0][j], acc[0][j]), mul2(acc[1][j], acc[1][j])),
                         add2(mul2(acc[2][j], acc[2][j]), mul2(acc[3][j], acc[3][j])));
            float2 fs = unpk(s), fq = unpk(q);
            ps[j]  = fs.x + fs.y;
            ps2[j] = fq.x + fq.y;
        }
        #pragma unroll
        for (int j = 0; j < 8; j++) {
            ps[j]  += __shfl_down_sync(0xffffffffu, ps[j], 16);
            ps2[j] += __shfl_down_sync(0xffffffffu, ps2[j], 16);
        }
        int lane = tid & 31, wrp = tid >> 5;
        if (lane < 16) {
            #pragma unroll
            for (int j = 0; j < 8; j++) {
                As[wrp][tx*8 + j]     = ps[j];
                As[wrp + 8][tx*8 + j] = ps2[j];
            }
        }
        __syncthreads();
        if (tid < 128) {
            double s = 0.0, s2 = 0.0;
            #pragma unroll
            for (int w = 0; w < 8; w++) { s += As[w][tid]; s2 += As[w + 8][tid]; }
            atomicAdd(&g_dsum[stage][n0 + tid], s);
            atomicAdd(&g_dsum2[stage][n0 + tid], s2);
        }
    }
}

// ---------------- dist = sq[m]+sq[n]-2*k_m.k_n, per batch, FMA2 ----------------
__global__ __launch_bounds__(256)
void dist_kernel(const float* __restrict__ key, const float* __restrict__ sq,
                 float* __restrict__ dist)
{
    int b = blockIdx.z;
    const float* A  = key + (size_t)b * NPTS * C_;
    const float* sb = sq + b * NPTS;
    float* D = dist + (size_t)b * NPTS * NPTS;

    __shared__ __align__(16) float As[16][128];
    __shared__ __align__(16) float Wd[16][256];
    int tid = threadIdx.x;
    int tx = tid & 15, ty = tid >> 4;
    int m0 = blockIdx.y * 128, n0 = blockIdx.x * 128;
    int lr = tid >> 2;
    int lc = (tid & 3) << 2;
    ull acc[4][8] = {};

    for (int k0 = 0; k0 < C_; k0 += 16) {
        float4 a0 = *(const float4*)&A[(size_t)(m0 + lr)      * C_ + k0 + lc];
        float4 a1 = *(const float4*)&A[(size_t)(m0 + lr + 64) * C_ + k0 + lc];
        float4 w0 = *(const float4*)&A[(size_t)(n0 + lr)      * C_ + k0 + lc];
        float4 w1 = *(const float4*)&A[(size_t)(n0 + lr + 64) * C_ + k0 + lc];
        As[lc+0][lr] = a0.x; As[lc+1][lr] = a0.y; As[lc+2][lr] = a0.z; As[lc+3][lr] = a0.w;
        As[lc+0][lr+64] = a1.x; As[lc+1][lr+64] = a1.y; As[lc+2][lr+64] = a1.z; As[lc+3][lr+64] = a1.w;
        *(ull*)&Wd[lc+0][2*lr] = dup2(w0.x);
        *(ull*)&Wd[lc+1][2*lr] = dup2(w0.y);
        *(ull*)&Wd[lc+2][2*lr] = dup2(w0.z);
        *(ull*)&Wd[lc+3][2*lr] = dup2(w0.w);
        *(ull*)&Wd[lc+0][2*(lr+64)] = dup2(w1.x);
        *(ull*)&Wd[lc+1][2*(lr+64)] = dup2(w1.y);
        *(ull*)&Wd[lc+2][2*(lr+64)] = dup2(w1.z);
        *(ull*)&Wd[lc+3][2*(lr+64)] = dup2(w1.w);
        __syncthreads();
        #pragma unroll
        for (int kk = 0; kk < 16; kk++) {
            ulonglong2 aA = *(const ulonglong2*)&As[kk][ty*8];
            ulonglong2 aB = *(const ulonglong2*)&As[kk][ty*8 + 4];
            ull ap[4] = { aA.x, aA.y, aB.x, aB.y };
            ulonglong2 v0 = *(const ulonglong2*)&Wd[kk][16*tx];
            ulonglong2 v1 = *(const ulonglong2*)&Wd[kk][16*tx + 4];
            ulonglong2 v2 = *(const ulonglong2*)&Wd[kk][16*tx + 8];
            ulonglong2 v3 = *(const ulonglong2*)&Wd[kk][16*tx + 12];
            ull wp[8] = { v0.x, v0.y, v1.x, v1.y, v2.x, v2.y, v3.x, v3.y };
            #pragma unroll
            for (int i2 = 0; i2 < 4; i2++)
                #pragma unroll
                for (int j = 0; j < 8; j++)
                    fma2(acc[i2][j], ap[i2], wp[j]);
        }
        __syncthreads();
    }
    float sn[8];
    *(float4*)(sn)     = *(const float4*)&sb[n0 + tx*8];
    *(float4*)(sn + 4) = *(const float4*)&sb[n0 + tx*8 + 4];
    #pragma unroll
    for (int i2 = 0; i2 < 4; i2++) {
        int gm0 = m0 + ty*8 + 2*i2;
        float sm0 = sb[gm0], sm1 = sb[gm0 + 1];
        float2 p[8];
        #pragma unroll
        for (int j = 0; j < 8; j++) p[j] = unpk(acc[i2][j]);
        float o0[8], o1[8];
        #pragma unroll
        for (int j = 0; j < 8; j++) {
            o0[j] = sm0 + sn[j] - 2.f * p[j].x;
            o1[j] = sm1 + sn[j] - 2.f * p[j].y;
        }
        size_t r0 = (size_t)gm0 * NPTS + n0 + tx*8;
        *(float4*)&D[r0]            = *(float4*)(o0);
        *(float4*)&D[r0 + 4]        = *(float4*)(o0 + 4);
        *(float4*)&D[r0 + NPTS]     = *(float4*)(o1);
        *(float4*)&D[r0 + NPTS + 4] = *(float4*)(o1 + 4);
    }
}

// ---------------- sq[row] = sum_d key[row,d]^2 ----------------
__global__ void sq_kernel(const float* __restrict__ key, float* __restrict__ sq)
{
    int w = (blockIdx.x * blockDim.x + threadIdx.x) >> 5;
    int lane = threadIdx.x & 31;
    if (w < M1) {
        const float* p = key + (size_t)w * C_;
        float s = 0.f;
        for (int d = lane; d < C_; d += 32) { float v = p[d]; s += v * v; }
        #pragma unroll
        for (int o = 16; o; o >>= 1) s += __shfl_down_sync(0xffffffffu, s, o);
        if (lane == 0) sq[w] = s;
    }
}

// ---------------- top-32 smallest per row: per-thread sorted lists + extraction ----------------
#define CE(i,j) { if (vr[j] < vr[i] || (vr[j] == vr[i] && idr[j] < idr[i])) { \
                    float tv = vr[i]; vr[i] = vr[j]; vr[j] = tv; \
                    int ti = idr[i]; idr[i] = idr[j]; idr[j] = ti; } }

__global__ __launch_bounds__(256)
void topk_kernel(const float* __restrict__ dist)
{
    int bn = blockIdx.x;
    const float* row = dist + (size_t)bn * NPTS;
    int t = threadIdx.x;
    int lane = t & 31, wrp = t >> 5;

    float vr[8]; int idr[8];
    #pragma unroll
    for (int s = 0; s < 8; s++) {
        int j = s * 256 + t;
        vr[s] = row[j]; idr[s] = j;
    }
    // Batcher odd-even merge sort, 19 CEs, ascending (v, idx)
    CE(0,1) CE(2,3) CE(4,5) CE(6,7)
    CE(0,2) CE(1,3) CE(4,6) CE(5,7)
    CE(1,2) CE(5,6)
    CE(0,4) CE(1,5) CE(2,6) CE(3,7)
    CE(2,4) CE(3,5)
    CE(1,2) CE(3,4) CE(5,6)

    __shared__ float swv[8];
    __shared__ int   swi[8];
    __shared__ int   swinner;

    for (int sel = 0; sel < KNB; sel++) {
        float cv = vr[0]; int ci = idr[0];
        #pragma unroll
        for (int o = 16; o; o >>= 1) {
            float ov = __shfl_down_sync(0xffffffffu, cv, o);
            int   oi = __shfl_down_sync(0xffffffffu, ci, o);
            if (ov < cv || (ov == cv && oi < ci)) { cv = ov; ci = oi; }
        }
        if (lane == 0) { swv[wrp] = cv; swi[wrp] = ci; }
        __syncthreads();
        if (t == 0) {
            float bv = swv[0]; int bi = swi[0];
            #pragma unroll
            for (int w = 1; w < 8; w++)
                if (swv[w] < bv || (swv[w] == bv && swi[w] < bi)) { bv = swv[w]; bi = swi[w]; }
            g_idx[(size_t)bn * KNB + sel] = bi;
            swinner = bi;
        }
        __syncthreads();
        if (idr[0] == swinner) {
            #pragma unroll
            for (int s = 0; s < 7; s++) { vr[s] = vr[s+1]; idr[s] = idr[s+1]; }
            vr[7] = FLT_MAX; idr[7] = 0x7fffffff;
        }
    }
}

// ---------------- stats infra ----------------
__global__ void zero_all_stats()
{
    int i = blockIdx.x * 256 + threadIdx.x;
    if (i < 8 * HID) { ((double*)g_dsum)[i] = 0.0; ((double*)g_dsum2)[i] = 0.0; }
}

__global__ void stats_finalize_fold(const float* __restrict__ gamma, const float* __restrict__ beta,
                                    int M, int D, int stage)
{
    int d = blockIdx.x * blockDim.x + threadIdx.x;
    if (d < D) {
        double m = g_dsum[stage][d] / (double)M;
        double v = g_dsum2[stage][d] / (double)M - m * m;
        if (v < 0.0) v = 0.0;
        float a = gamma[d] * rsqrtf((float)v + EPSB);
        g_afa[stage][d] = a;
        g_afc[stage][d] = beta[d] - (float)m * a;
    }
}

// ---------------- posb_raw stats: val = P[jg,d] - P[bn,d] over all (bn,k) ----------------
__global__ __launch_bounds__(256)
void pbstats_kernel(const float* __restrict__ P)
{
    int d = threadIdx.x;
    int rows = M2 / gridDim.x;
    int r0 = blockIdx.x * rows;
    float s = 0.f, s2 = 0.f;
    for (int r = r0; r < r0 + rows; r++) {
        int bn = r >> 5;
        int b  = r >> 16;
        int jg = (b << 11) + g_idx[r];
        float val = P[(size_t)jg * C_ + d] - P[(size_t)bn * C_ + d];
        s += val; s2 += val * val;
    }
    atomicAdd(&g_dsum[ST_PB][d],  (double)s);
    atomicAdd(&g_dsum2[ST_PB][d], (double)s2);
}

// ---------------- BN apply ----------------
__global__ void bn_leaky_apply3(const float* __restrict__ Y, float* __restrict__ out)
{
    size_t e = (size_t)blockIdx.x * blockDim.x + threadIdx.x;
    const size_t total = (size_t)3 * M1 * C_;
    if (e < total) {
        int d = (int)(e & (C_ - 1));
        int stage = ST_Q + (int)(e >> 20);   // M1*C_ = 2^20
        float z = g_afa[stage][d] * Y[e] + g_afc[stage][d];
        out[e] = lrelu(z);
    }
}

__global__ void bn_silu_res_apply(const float* __restrict__ Y, const float* __restrict__ res,
                                  float* __restrict__ out)
{
    size_t e = (size_t)blockIdx.x * blockDim.x + threadIdx.x;
    const size_t total = (size_t)M1 * C_;
    if (e < total) {
        int d = (int)(e & (C_ - 1));
        float z = g_afa[ST_M2][d] * Y[e] + g_afc[ST_M2][d];
        out[e] = res[e] + z / (1.f + expf(-z));
    }
}

// ---------------- vec1: s1_raw = vecin @ We1^T, gather-fused A, FMA2, fused stats ----------------
__global__ __launch_bounds__(256)
void vec1_kernel(const float* __restrict__ qb, const float* __restrict__ kb,
                 const float* __restrict__ P,  const float* __restrict__ We1,
                 float* __restrict__ s1)
{
    __shared__ __align__(16) float As[16][128];
    __shared__ __align__(16) float Wsd[16][64];
    __shared__ int sj[128];
    __shared__ float cs[8][32], cs2[8][32];
    int tid = threadIdx.x;
    int m0 = blockIdx.x * 128;
    if (tid < 128) sj[tid] = g_idx[m0 + tid];
    __syncthreads();

    int tx = tid & 15, ty = tid >> 4;
    int lr = tid >> 2;
    int lc = (tid & 3) << 2;
    int r0 = m0 + lr,      bn0 = r0 >> 5, b0 = r0 >> 16;
    int r1 = m0 + lr + 64, bn1 = r1 >> 5, b1 = r1 >> 16;
    int jg0 = (b0 << 11) + sj[lr];
    int jg1 = (b1 << 11) + sj[lr + 64];
    ull acc[4][2] = {};

    for (int k0 = 0; k0 < C_; k0 += 16) {
        #pragma unroll
        for (int h = 0; h < 2; h++) {
            int jg = h ? jg1 : jg0;
            int bn = h ? bn1 : bn0;
            int rr = h ? lr + 64 : lr;
            float4 kf = *(const float4*)&kb[(size_t)jg * C_ + k0 + lc];
            float4 qf = *(const float4*)&qb[(size_t)bn * C_ + k0 + lc];
            float4 pj = *(const float4*)&P [(size_t)jg * C_ + k0 + lc];
            float4 pn = *(const float4*)&P [(size_t)bn * C_ + k0 + lc];
            float4 pa = *(const float4*)&g_afa[ST_PB][k0 + lc];
            float4 pc = *(const float4*)&g_afc[ST_PB][k0 + lc];
            As[lc+0][rr] = kf.x - qf.x + lrelu(pa.x * (pj.x - pn.x) + pc.x);
            As[lc+1][rr] = kf.y - qf.y + lrelu(pa.y * (pj.y - pn.y) + pc.y);
            As[lc+2][rr] = kf.z - qf.z + lrelu(pa.z * (pj.z - pn.z) + pc.z);
            As[lc+3][rr] = kf.w - qf.w + lrelu(pa.w * (pj.w - pn.w) + pc.w);
        }
        {
            int i0 = tid;           // 512 vals: g = i&31, kk = i>>5
            *(ull*)&Wsd[i0 >> 5][2*(i0 & 31)] = dup2(We1[(size_t)(i0 & 31) * C_ + k0 + (i0 >> 5)]);
            int i1 = tid + 256;
            *(ull*)&Wsd[i1 >> 5][2*(i1 & 31)] = dup2(We1[(size_t)(i1 & 31) * C_ + k0 + (i1 >> 5)]);
        }
        __syncthreads();
        #pragma unroll
        for (int kk = 0; kk < 16; kk++) {
            ulonglong2 aA = *(const ulonglong2*)&As[kk][ty*8];
            ulonglong2 aB = *(const ulonglong2*)&As[kk][ty*8 + 4];
            ull ap[4] = { aA.x, aA.y, aB.x, aB.y };
            ulonglong2 wv = *(const ulonglong2*)&Wsd[kk][4*tx];
            #pragma unroll
            for (int i2 = 0; i2 < 4; i2++) {
                fma2(acc[i2][0], ap[i2], wv.x);
                fma2(acc[i2][1], ap[i2], wv.y);
            }
        }
        __syncthreads();
    }
    #pragma unroll
    for (int i2 = 0; i2 < 4; i2++) {
        float2 p0 = unpk(acc[i2][0]), p1 = unpk(acc[i2][1]);
        size_t w0 = (size_t)(m0 + ty*8 + 2*i2) * CPH + tx*2;
        s1[w0]           = p0.x; s1[w0 + 1]       = p1.x;
        s1[w0 + CPH]     = p0.y; s1[w0 + CPH + 1] = p1.y;
    }
    // fused stats (stage S1)
    float ps[2], ps2[2];
    #pragma unroll
    for (int j = 0; j < 2; j++) {
        ull s = add2(add2(acc[0][j], acc[1][j]), add2(acc[2][j], acc[3][j]));
        ull q = add2(add2(mul2(acc[0][j], acc[0][j]), mul2(acc[1][j], acc[1][j])),
                     add2(mul2(acc[2][j], acc[2][j]), mul2(acc[3][j], acc[3][j])));
        float2 fs = unpk(s), fq = unpk(q);
        ps[j] = fs.x + fs.y; ps2[j] = fq.x + fq.y;
    }
    ps[0]  += __shfl_down_sync(0xffffffffu, ps[0], 16);
    ps[1]  += __shfl_down_sync(0xffffffffu, ps[1], 16);
    ps2[0] += __shfl_down_sync(0xffffffffu, ps2[0], 16);
    ps2[1] += __shfl_down_sync(0xffffffffu, ps2[1], 16);
    int lane = tid & 31, wrp = tid >> 5;
    if (lane < 16) {
        cs[wrp][tx*2]      = ps[0];  cs[wrp][tx*2 + 1]  = ps[1];
        cs2[wrp][tx*2]     = ps2[0]; cs2[wrp][tx*2 + 1] = ps2[1];
    }
    __syncthreads();
    if (tid < 32) {
        double s = 0.0, s2 = 0.0;
        #pragma unroll
        for (int w = 0; w < 8; w++) { s += cs[w][tid]; s2 += cs2[w][tid]; }
        atomicAdd(&g_dsum[ST_S1][tid], s);
        atomicAdd(&g_dsum2[ST_S1][tid], s2);
    }
}

// ---------------- vec2: s2_raw = leaky(bn(s1)) @ We2^T, FMA2, fused stats ----------------
__global__ __launch_bounds__(256)
void vec2_kernel(const float* __restrict__ s1, const float* __restrict__ We2,
                 float* __restrict__ s2)
{
    __shared__ __align__(16) float As[16][128];
    __shared__ __align__(16) float Wsd[16][64];
    __shared__ float cs[8][32], cs2[8][32];
    int tid = threadIdx.x;
    int m0 = blockIdx.x * 128;
    int tx = tid & 15, ty = tid >> 4;
    int lr = tid >> 2;
    int lc = (tid & 3) << 2;
    ull acc[4][2] = {};

    for (int k0 = 0; k0 < CPH; k0 += 16) {
        #pragma unroll
        for (int h = 0; h < 2; h++) {
            int rr = h ? lr + 64 : lr;
            float4 y  = *(const float4*)&s1[(size_t)(m0 + rr) * CPH + k0 + lc];
            float4 aa = *(const float4*)&g_afa[ST_S1][k0 + lc];
            float4 cc = *(const float4*)&g_afc[ST_S1][k0 + lc];
            As[lc+0][rr] = lrelu(aa.x * y.x + cc.x);
            As[lc+1][rr] = lrelu(aa.y * y.y + cc.y);
            As[lc+2][rr] = lrelu(aa.z * y.z + cc.z);
            As[lc+3][rr] = lrelu(aa.w * y.w + cc.w);
        }
        {
            int i0 = tid;
            *(ull*)&Wsd[i0 >> 5][2*(i0 & 31)] = dup2(We2[(size_t)(i0 & 31) * CPH + k0 + (i0 >> 5)]);
            int i1 = tid + 256;
            *(ull*)&Wsd[i1 >> 5][2*(i1 & 31)] = dup2(We2[(size_t)(i1 & 31) * CPH + k0 + (i1 >> 5)]);
        }
        __syncthreads();
        #pragma unroll
        for (int kk = 0; kk < 16; kk++) {
            ulonglong2 aA = *(const ulonglong2*)&As[kk][ty*8];
            ulonglong2 aB = *(const ulonglong2*)&As[kk][ty*8 + 4];
            ull ap[4] = { aA.x, aA.y, aB.x, aB.y };
            ulonglong2 wv = *(const ulonglong2*)&Wsd[kk][4*tx];
            #pragma unroll
            for (int i2 = 0; i2 < 4; i2++) {
                fma2(acc[i2][0], ap[i2], wv.x);
                fma2(acc[i2][1], ap[i2], wv.y);
            }
        }
        __syncthreads();
    }
    #pragma unroll
    for (int i2 = 0; i2 < 4; i2++) {
        float2 p0 = unpk(acc[i2][0]), p1 = unpk(acc[i2][1]);
        size_t w0 = (size_t)(m0 + ty*8 + 2*i2) * CPH + tx*2;
        s2[w0]           = p0.x; s2[w0 + 1]       = p1.x;
        s2[w0 + CPH]     = p0.y; s2[w0 + CPH + 1] = p1.y;
    }
    float ps[2], ps2[2];
    #pragma unroll
    for (int j = 0; j < 2; j++) {
        ull s = add2(add2(acc[0][j], acc[1][j]), add2(acc[2][j], acc[3][j]));
        ull q = add2(add2(mul2(acc[0][j], acc[0][j]), mul2(acc[1][j], acc[1][j])),
                     add2(mul2(acc[2][j], acc[2][j]), mul2(acc[3][j], acc[3][j])));
        float2 fs = unpk(s), fq = unpk(q);
        ps[j] = fs.x + fs.y; ps2[j] = fq.x + fq.y;
    }
    ps[0]  += __shfl_down_sync(0xffffffffu, ps[0], 16);
    ps[1]  += __shfl_down_sync(0xffffffffu, ps[1], 16);
    ps2[0] += __shfl_down_sync(0xffffffffu, ps2[0], 16);
    ps2[1] += __shfl_down_sync(0xffffffffu, ps2[1], 16);
    int lane = tid & 31, wrp = tid >> 5;
    if (lane < 16) {
        cs[wrp][tx*2]      = ps[0];  cs[wrp][tx*2 + 1]  = ps[1];
        cs2[wrp][tx*2]     = ps2[0]; cs2[wrp][tx*2 + 1] = ps2[1];
    }
    __syncthreads();
    if (tid < 32) {
        double s = 0.0, s2 = 0.0;
        #pragma unroll
        for (int w = 0; w < 8; w++) { s += cs[w][tid]; s2 += cs2[w][tid]; }
        atomicAdd(&g_dsum[ST_S2][tid], s);
        atomicAdd(&g_dsum2[ST_S2][tid], s2);
    }
}

// ---------------- attention: BN+leaky(s2) -> softmax over k -> combine + residual ----------------
__global__ __launch_bounds__(256)
void attn_kernel(const float* __restrict__ x, const float* __restrict__ s2,
                 const float* __restrict__ vb, const float* __restrict__ P,
                 float* __restrict__ xattn)
{
    int bn = blockIdx.x;
    int t = threadIdx.x;
    __shared__ float soft[KNB][CPH + 1];
    __shared__ int sj[KNB];
    size_t base = (size_t)bn * KNB * CPH;
    for (int e = t; e < KNB * CPH; e += 256) {
        int g = e & 31;
        float y = s2[base + e];
        soft[e >> 5][g] = lrelu(g_afa[ST_S2][g] * y + g_afc[ST_S2][g]);
    }
    if (t < KNB) sj[t] = g_idx[(size_t)bn * KNB + t];
    __syncthreads();
    if (t < CPH) {
        float mx = -FLT_MAX;
        #pragma unroll
        for (int k = 0; k < KNB; k++) mx = fmaxf(mx, soft[k][t]);
        float s = 0.f;
        #pragma unroll
        for (int k = 0; k < KNB; k++) { float ev = expf(soft[k][t] - mx); soft[k][t] = ev; s += ev; }
        float inv = 1.f / s;
        #pragma unroll
        for (int k = 0; k < KNB; k++) soft[k][t] *= inv;
    }
    __syncthreads();

    int c = t, g = t >> 3;
    int b = bn >> 11;
    float pn = P[(size_t)bn * C_ + c];
    float pa = g_afa[ST_PB][c], pc = g_afc[ST_PB][c];
    float acc = 0.f;
    #pragma unroll
    for (int k = 0; k < KNB; k++) {
        int jg = (b << 11) + sj[k];
        float posb = lrelu(pa * (P[(size_t)jg * C_ + c] - pn) + pc);
        acc += (vb[(size_t)jg * C_ + c] + posb) * soft[k][g];
    }
    size_t o = (size_t)bn * C_ + c;
    xattn[o] = x[o] + acc;
}

extern "C" void kernel_launch(void* const* d_in, const int* in_sizes, int n_in,
                              void* d_out, int out_size)
{
    const float* x   = (const float*)d_in[0];
    const float* pos = (const float*)d_in[1];
    const float* Wq  = (const float*)d_in[2];
    const float* gq  = (const float*)d_in[3];
    const float* bq  = (const float*)d_in[4];
    const float* Wk  = (const float*)d_in[5];
    const float* gk  = (const float*)d_in[6];
    const float* bk  = (const float*)d_in[7];
    const float* Wv  = (const float*)d_in[8];
    const float* gv  = (const float*)d_in[9];
    const float* bv  = (const float*)d_in[10];
    const float* Wpb = (const float*)d_in[11];
    const float* gpb = (const float*)d_in[12];
    const float* bpb = (const float*)d_in[13];
    const float* We1 = (const float*)d_in[14];
    const float* ge1 = (const float*)d_in[15];
    const float* be1 = (const float*)d_in[16];
    const float* We2 = (const float*)d_in[17];
    const float* ge2 = (const float*)d_in[18];
    const float* be2 = (const float*)d_in[19];
    const float* Wm1 = (const float*)d_in[20];
    const float* gm1 = (const float*)d_in[21];
    const float* bm1 = (const float*)d_in[22];
    const float* Wm2 = (const float*)d_in[23];
    const float* gm2 = (const float*)d_in[24];
    const float* bm2 = (const float*)d_in[25];
    float* out = (float*)d_out;

    void* p;
    float *qkv, *tmp, *sqv, *dist, *s1, *s2, *xatt;
    cudaGetSymbolAddress(&p, g_qkv);   qkv  = (float*)p;
    cudaGetSymbolAddress(&p, g_tmp4);  tmp  = (float*)p;
    cudaGetSymbolAddress(&p, g_sqv);   sqv  = (float*)p;
    cudaGetSymbolAddress(&p, g_dist);  dist = (float*)p;
    cudaGetSymbolAddress(&p, g_s1);    s1   = (float*)p;
    cudaGetSymbolAddress(&p, g_s2);    s2   = (float*)p;
    cudaGetSymbolAddress(&p, g_xattn); xatt = (float*)p;

    const size_t SL = (size_t)M1 * C_;       // 2^20
    float* t0 = tmp;          // raw q -> MLP1 raw
    float* t1 = tmp + SL;     // raw k
    float* t2 = tmp + 2*SL;   // raw v -> MLP2 raw
    float* t3 = tmp + 3*SL;   // P = pos @ Wpb^T
    float* qb = qkv;
    float* kb = qkv + SL;
    float* vb = qkv + 2*SL;

    const int BLK = 256;

    // 0. zero stats accumulators
    zero_all_stats<<<16, 256>>>();

    // 1. batched GEMM: q,k,v raw (stats fused) + P
    {
        Gemm4 g = { { x, x, x, pos }, { Wq, Wk, Wv, Wpb }, { t0, t1, t2, t3 },
                    { ST_Q, ST_K, ST_V, -1 } };
        gemm128_kernel<<<dim3(C_/128, M1/128, 4), 256>>>(g, C_, C_, 0);
    }
    stats_finalize_fold<<<1, 256>>>(gq, bq, M1, C_, ST_Q);
    stats_finalize_fold<<<1, 256>>>(gk, bk, M1, C_, ST_K);
    stats_finalize_fold<<<1, 256>>>(gv, bv, M1, C_, ST_V);
    bn_leaky_apply3<<<(int)((3*SL + BLK - 1) / BLK), BLK>>>(tmp, qkv);

    // 2. kNN
    sq_kernel<<<(M1 * 32 + BLK - 1) / BLK, BLK>>>(kb, sqv);
    dist_kernel<<<dim3(NPTS/128, NPTS/128, B_), 256>>>(kb, sqv, dist);
    topk_kernel<<<M1, 256>>>(dist);

    // 3. posb stats (unmaterialized P[j]-P[n])
    pbstats_kernel<<<256, 256>>>(t3);
    stats_finalize_fold<<<1, 256>>>(gpb, bpb, M2, C_, ST_PB);

    // 4. vector path (stats fused into epilogues)
    vec1_kernel<<<M2/128, 256>>>(qb, kb, t3, We1, s1);
    stats_finalize_fold<<<1, 256>>>(ge1, be1, M2, CPH, ST_S1);
    vec2_kernel<<<M2/128, 256>>>(s1, We2, s2);
    stats_finalize_fold<<<1, 256>>>(ge2, be2, M2, CPH, ST_S2);

    // 5. attention + residual
    attn_kernel<<<M1, 256>>>(x, s2, vb, t3, xatt);

    // 6. MLP (stats fused; silu(bn) of MLP1 fused into MLP2 A-load)
    {
        Gemm4 g = { { xatt, 0, 0, 0 }, { Wm1, 0, 0, 0 }, { t0, 0, 0, 0 },
                    { ST_M1, -1, -1, -1 } };
        gemm128_kernel<<<dim3(HID/128, M1/128, 1), 256>>>(g, HID, C_, 0);
    }
    stats_finalize_fold<<<2, 256>>>(gm1, bm1, M1, HID, ST_M1);
    {
        Gemm4 g = { { t0, 0, 0, 0 }, { Wm2, 0, 0, 0 }, { t2, 0, 0, 0 },
                    { ST_M2, -1, -1, -1 } };
        gemm128_kernel<<<dim3(C_/128, M1/128, 1), 256>>>(g, C_, HID, 1);
    }
    stats_finalize_fold<<<1, 256>>>(gm2, bm2, M1, C_, ST_M2);
    bn_silu_res_apply<<<(int)((SL + BLK - 1) / BLK), BLK>>>(t2, xatt, out);
}

// round 6
// speedup vs baseline: 3.1198x; 1.5803x over previous
#include <cuda_runtime.h>
#include <math.h>
#include <float.h>

#define B_   2
#define NPTS 2048
#define C_   256
#define KNB  32
#define HID  512
#define CPH  32
#define M1   (B_*NPTS)        // 4096
#define M2   (B_*NPTS*KNB)    // 131072
#define EPSB 1e-5f

#define ST_Q  0
#define ST_K  1
#define ST_V  2
#define ST_PB 3
#define ST_S1 4
#define ST_S2 5
#define ST_M1 6
#define ST_M2 7

typedef unsigned long long ull;

// ---------------- device scratch ----------------
__device__ float g_qkv[3*M1*C_];               // q, k, v (BN applied)
__device__ float g_tmp4[(size_t)M1*C_*4];      // raw q,k,v + P; reused for MLP raws
__device__ float g_sqv[M1];
__device__ float g_dist[(size_t)B_*NPTS*NPTS];
__device__ int   g_idx[M2];
__device__ float g_s1[(size_t)M2*CPH];
__device__ float g_s2[(size_t)M2*CPH];
__device__ float g_xattn[M1*C_];
__device__ double g_dsum[8][HID];
__device__ double g_dsum2[8][HID];
__device__ float g_afa[8][HID];
__device__ float g_afc[8][HID];

__device__ __forceinline__ float lrelu(float z) { return z >= 0.f ? z : 0.2f * z; }

// ---------------- packed f32x2 helpers ----------------
__device__ __forceinline__ void fma2(ull& d, ull a, ull b) {
    asm("fma.rn.f32x2 %0, %1, %2, %0;" : "+l"(d) : "l"(a), "l"(b));
}
__device__ __forceinline__ ull add2(ull a, ull b) {
    ull d; asm("add.rn.f32x2 %0, %1, %2;" : "=l"(d) : "l"(a), "l"(b)); return d;
}
__device__ __forceinline__ ull mul2(ull a, ull b) {
    ull d; asm("mul.rn.f32x2 %0, %1, %2;" : "=l"(d) : "l"(a), "l"(b)); return d;
}
__device__ __forceinline__ ull dup2(float x) {
    ull r; asm("mov.b64 %0, {%1, %1};" : "=l"(r) : "f"(x)); return r;
}
__device__ __forceinline__ float2 unpk(ull v) {
    float2 f; asm("mov.b64 {%0, %1}, %2;" : "=f"(f.x), "=f"(f.y) : "l"(v)); return f;
}

// XOR swizzle for the duplicated-W tile (row = 256 floats = 64 quads).
// Quad p -> p ^ ((p>>3)&7): spreads the reader's 64B-stride access over all 8 bank quads.
__device__ __forceinline__ int swzW(int f) {
    int p = f >> 2;
    return (((p ^ ((p >> 3) & 7)) << 2) | (f & 3));
}

// ---------------- batched TN GEMM, FMA2, fused stats, optional silu-A ----------------
// C[m,n] = sum_k T(A[m,k]) * W[n,k].  BM=BN=128, BK=16, 256 thr, 8x8/thread.
struct Gemm4 {
    const float* A[4];
    const float* W[4];
    float*       C[4];
    int          stage[4];   // -1 = no stats
};

__global__ __launch_bounds__(256)
void gemm128_kernel(Gemm4 g, int N, int K, int dosilu)
{
    __shared__ __align__(16) float As[16][128];
    __shared__ __align__(16) float Wd[16][256];
    int z = blockIdx.z;
    const float* A = g.A[z];
    const float* W = g.W[z];
    float*       C = g.C[z];
    int stage = g.stage[z];
    int tid = threadIdx.x;
    int tx = tid & 15, ty = tid >> 4;
    int m0 = blockIdx.y * 128, n0 = blockIdx.x * 128;
    int lr = tid >> 2;
    int lc = (tid & 3) << 2;
    ull acc[4][8] = {};

    int wq0 = swzW(2*lr);          // swizzled float offsets (writes)
    int wq1 = swzW(2*(lr+64));
    int rq0 = swzW(16*tx);         // swizzled float offsets (reads)
    int rq1 = swzW(16*tx + 4);
    int rq2 = swzW(16*tx + 8);
    int rq3 = swzW(16*tx + 12);

    for (int k0 = 0; k0 < K; k0 += 16) {
        float4 a0 = *(const float4*)&A[(size_t)(m0 + lr)      * K + k0 + lc];
        float4 a1 = *(const float4*)&A[(size_t)(m0 + lr + 64) * K + k0 + lc];
        if (dosilu) {
            #pragma unroll
            for (int i = 0; i < 4; i++) {
                float aa = g_afa[ST_M1][k0 + lc + i];
                float cc = g_afc[ST_M1][k0 + lc + i];
                float* pz = (i==0)?&a0.x:(i==1)?&a0.y:(i==2)?&a0.z:&a0.w;
                float* pw = (i==0)?&a1.x:(i==1)?&a1.y:(i==2)?&a1.z:&a1.w;
                float z0 = aa * (*pz) + cc; *pz = z0 / (1.f + __expf(-z0));
                float z1 = aa * (*pw) + cc; *pw = z1 / (1.f + __expf(-z1));
            }
        }
        float4 w0 = *(const float4*)&W[(size_t)(n0 + lr)      * K + k0 + lc];
        float4 w1 = *(const float4*)&W[(size_t)(n0 + lr + 64) * K + k0 + lc];
        As[lc+0][lr] = a0.x; As[lc+1][lr] = a0.y; As[lc+2][lr] = a0.z; As[lc+3][lr] = a0.w;
        As[lc+0][lr+64] = a1.x; As[lc+1][lr+64] = a1.y; As[lc+2][lr+64] = a1.z; As[lc+3][lr+64] = a1.w;
        *(ull*)&Wd[lc+0][wq0] = dup2(w0.x);
        *(ull*)&Wd[lc+1][wq0] = dup2(w0.y);
        *(ull*)&Wd[lc+2][wq0] = dup2(w0.z);
        *(ull*)&Wd[lc+3][wq0] = dup2(w0.w);
        *(ull*)&Wd[lc+0][wq1] = dup2(w1.x);
        *(ull*)&Wd[lc+1][wq1] = dup2(w1.y);
        *(ull*)&Wd[lc+2][wq1] = dup2(w1.z);
        *(ull*)&Wd[lc+3][wq1] = dup2(w1.w);
        __syncthreads();
        #pragma unroll
        for (int kk = 0; kk < 16; kk++) {
            ulonglong2 aA = *(const ulonglong2*)&As[kk][ty*8];
            ulonglong2 aB = *(const ulonglong2*)&As[kk][ty*8 + 4];
            ull ap[4] = { aA.x, aA.y, aB.x, aB.y };
            ulonglong2 v0 = *(const ulonglong2*)&Wd[kk][rq0];
            ulonglong2 v1 = *(const ulonglong2*)&Wd[kk][rq1];
            ulonglong2 v2 = *(const ulonglong2*)&Wd[kk][rq2];
            ulonglong2 v3 = *(const ulonglong2*)&Wd[kk][rq3];
            ull wp[8] = { v0.x, v0.y, v1.x, v1.y, v2.x, v2.y, v3.x, v3.y };
            #pragma unroll
            for (int i2 = 0; i2 < 4; i2++)
                #pragma unroll
                for (int j = 0; j < 8; j++)
                    fma2(acc[i2][j], ap[i2], wp[j]);
        }
        __syncthreads();
    }

    // store C
    #pragma unroll
    for (int i2 = 0; i2 < 4; i2++) {
        float2 p[8];
        #pragma unroll
        for (int j = 0; j < 8; j++) p[j] = unpk(acc[i2][j]);
        size_t r0 = (size_t)(m0 + ty*8 + 2*i2) * N + n0 + tx*8;
        size_t r1 = r0 + N;
        *(float4*)&C[r0]     = make_float4(p[0].x, p[1].x, p[2].x, p[3].x);
        *(float4*)&C[r0 + 4] = make_float4(p[4].x, p[5].x, p[6].x, p[7].x);
        *(float4*)&C[r1]     = make_float4(p[0].y, p[1].y, p[2].y, p[3].y);
        *(float4*)&C[r1 + 4] = make_float4(p[4].y, p[5].y, p[6].y, p[7].y);
    }

    // fused stats: column sums/sumsq over the 128 rows of this block
    if (stage >= 0) {
        float ps[8], ps2[8];
        #pragma unroll
        for (int j = 0; j < 8; j++) {
            ull s = add2(add2(acc[0][j], acc[1][j]), add2(acc[2][j], acc[3][j]));
            ull q = add2(add2(mul2(acc[0][j], acc[0][j]), mul2(acc[1][j], acc[1][j])),
                         add2(mul2(acc[2][j], acc[2][j]), mul2(acc[3][j], acc[3][j])));
            float2 fs = unpk(s), fq = unpk(q);
            ps[j]  = fs.x + fs.y;
            ps2[j] = fq.x + fq.y;
        }
        #pragma unroll
        for (int j = 0; j < 8; j++) {
            ps[j]  += __shfl_down_sync(0xffffffffu, ps[j], 16);
            ps2[j] += __shfl_down_sync(0xffffffffu, ps2[j], 16);
        }
        int lane = tid & 31, wrp = tid >> 5;
        if (lane < 16) {
            #pragma unroll
            for (int j = 0; j < 8; j++) {
                As[wrp][tx*8 + j]     = ps[j];
                As[wrp + 8][tx*8 + j] = ps2[j];
            }
        }
        __syncthreads();
        if (tid < 128) {
            double s = 0.0, s2 = 0.0;
            #pragma unroll
            for (int w = 0; w < 8; w++) { s += As[w][tid]; s2 += As[w + 8][tid]; }
            atomicAdd(&g_dsum[stage][n0 + tid], s);
            atomicAdd(&g_dsum2[stage][n0 + tid], s2);
        }
    }
}

// ---------------- dist = sq[m]+sq[n]-2*k_m.k_n, per batch, FMA2 + swizzled W ----------------
__global__ __launch_bounds__(256)
void dist_kernel(const float* __restrict__ key, const float* __restrict__ sq,
                 float* __restrict__ dist)
{
    int b = blockIdx.z;
    const float* A  = key + (size_t)b * NPTS * C_;
    const float* sb = sq + b * NPTS;
    float* D = dist + (size_t)b * NPTS * NPTS;

    __shared__ __align__(16) float As[16][128];
    __shared__ __align__(16) float Wd[16][256];
    int tid = threadIdx.x;
    int tx = tid & 15, ty = tid >> 4;
    int m0 = blockIdx.y * 128, n0 = blockIdx.x * 128;
    int lr = tid >> 2;
    int lc = (tid & 3) << 2;
    ull acc[4][8] = {};

    int wq0 = swzW(2*lr);
    int wq1 = swzW(2*(lr+64));
    int rq0 = swzW(16*tx);
    int rq1 = swzW(16*tx + 4);
    int rq2 = swzW(16*tx + 8);
    int rq3 = swzW(16*tx + 12);

    for (int k0 = 0; k0 < C_; k0 += 16) {
        float4 a0 = *(const float4*)&A[(size_t)(m0 + lr)      * C_ + k0 + lc];
        float4 a1 = *(const float4*)&A[(size_t)(m0 + lr + 64) * C_ + k0 + lc];
        float4 w0 = *(const float4*)&A[(size_t)(n0 + lr)      * C_ + k0 + lc];
        float4 w1 = *(const float4*)&A[(size_t)(n0 + lr + 64) * C_ + k0 + lc];
        As[lc+0][lr] = a0.x; As[lc+1][lr] = a0.y; As[lc+2][lr] = a0.z; As[lc+3][lr] = a0.w;
        As[lc+0][lr+64] = a1.x; As[lc+1][lr+64] = a1.y; As[lc+2][lr+64] = a1.z; As[lc+3][lr+64] = a1.w;
        *(ull*)&Wd[lc+0][wq0] = dup2(w0.x);
        *(ull*)&Wd[lc+1][wq0] = dup2(w0.y);
        *(ull*)&Wd[lc+2][wq0] = dup2(w0.z);
        *(ull*)&Wd[lc+3][wq0] = dup2(w0.w);
        *(ull*)&Wd[lc+0][wq1] = dup2(w1.x);
        *(ull*)&Wd[lc+1][wq1] = dup2(w1.y);
        *(ull*)&Wd[lc+2][wq1] = dup2(w1.z);
        *(ull*)&Wd[lc+3][wq1] = dup2(w1.w);
        __syncthreads();
        #pragma unroll
        for (int kk = 0; kk < 16; kk++) {
            ulonglong2 aA = *(const ulonglong2*)&As[kk][ty*8];
            ulonglong2 aB = *(const ulonglong2*)&As[kk][ty*8 + 4];
            ull ap[4] = { aA.x, aA.y, aB.x, aB.y };
            ulonglong2 v0 = *(const ulonglong2*)&Wd[kk][rq0];
            ulonglong2 v1 = *(const ulonglong2*)&Wd[kk][rq1];
            ulonglong2 v2 = *(const ulonglong2*)&Wd[kk][rq2];
            ulonglong2 v3 = *(const ulonglong2*)&Wd[kk][rq3];
            ull wp[8] = { v0.x, v0.y, v1.x, v1.y, v2.x, v2.y, v3.x, v3.y };
            #pragma unroll
            for (int i2 = 0; i2 < 4; i2++)
                #pragma unroll
                for (int j = 0; j < 8; j++)
                    fma2(acc[i2][j], ap[i2], wp[j]);
        }
        __syncthreads();
    }
    float sn[8];
    *(float4*)(sn)     = *(const float4*)&sb[n0 + tx*8];
    *(float4*)(sn + 4) = *(const float4*)&sb[n0 + tx*8 + 4];
    #pragma unroll
    for (int i2 = 0; i2 < 4; i2++) {
        int gm0 = m0 + ty*8 + 2*i2;
        float sm0 = sb[gm0], sm1 = sb[gm0 + 1];
        float2 p[8];
        #pragma unroll
        for (int j = 0; j < 8; j++) p[j] = unpk(acc[i2][j]);
        float o0[8], o1[8];
        #pragma unroll
        for (int j = 0; j < 8; j++) {
            o0[j] = sm0 + sn[j] - 2.f * p[j].x;
            o1[j] = sm1 + sn[j] - 2.f * p[j].y;
        }
        size_t r0 = (size_t)gm0 * NPTS + n0 + tx*8;
        *(float4*)&D[r0]            = *(float4*)(o0);
        *(float4*)&D[r0 + 4]        = *(float4*)(o0 + 4);
        *(float4*)&D[r0 + NPTS]     = *(float4*)(o1);
        *(float4*)&D[r0 + NPTS + 4] = *(float4*)(o1 + 4);
    }
}

// ---------------- sq[row] = sum_d key[row,d]^2 ----------------
__global__ void sq_kernel(const float* __restrict__ key, float* __restrict__ sq)
{
    int w = (blockIdx.x * blockDim.x + threadIdx.x) >> 5;
    int lane = threadIdx.x & 31;
    if (w < M1) {
        const float* p = key + (size_t)w * C_;
        float s = 0.f;
        for (int d = lane; d < C_; d += 32) { float v = p[d]; s += v * v; }
        #pragma unroll
        for (int o = 16; o; o >>= 1) s += __shfl_down_sync(0xffffffffu, s, o);
        if (lane == 0) sq[w] = s;
    }
}

// ---------------- top-32 smallest per row: per-thread sorted lists + extraction ----------------
#define CE(i,j) { if (vr[j] < vr[i] || (vr[j] == vr[i] && idr[j] < idr[i])) { \
                    float tv = vr[i]; vr[i] = vr[j]; vr[j] = tv; \
                    int ti = idr[i]; idr[i] = idr[j]; idr[j] = ti; } }

__global__ __launch_bounds__(256)
void topk_kernel(const float* __restrict__ dist)
{
    int bn = blockIdx.x;
    const float* row = dist + (size_t)bn * NPTS;
    int t = threadIdx.x;
    int lane = t & 31, wrp = t >> 5;

    float vr[8]; int idr[8];
    #pragma unroll
    for (int s = 0; s < 8; s++) {
        int j = s * 256 + t;
        vr[s] = row[j]; idr[s] = j;
    }
    CE(0,1) CE(2,3) CE(4,5) CE(6,7)
    CE(0,2) CE(1,3) CE(4,6) CE(5,7)
    CE(1,2) CE(5,6)
    CE(0,4) CE(1,5) CE(2,6) CE(3,7)
    CE(2,4) CE(3,5)
    CE(1,2) CE(3,4) CE(5,6)

    __shared__ float swv[8];
    __shared__ int   swi[8];
    __shared__ int   swinner;

    for (int sel = 0; sel < KNB; sel++) {
        float cv = vr[0]; int ci = idr[0];
        #pragma unroll
        for (int o = 16; o; o >>= 1) {
            float ov = __shfl_down_sync(0xffffffffu, cv, o);
            int   oi = __shfl_down_sync(0xffffffffu, ci, o);
            if (ov < cv || (ov == cv && oi < ci)) { cv = ov; ci = oi; }
        }
        if (lane == 0) { swv[wrp] = cv; swi[wrp] = ci; }
        __syncthreads();
        if (t == 0) {
            float bv = swv[0]; int bi = swi[0];
            #pragma unroll
            for (int w = 1; w < 8; w++)
                if (swv[w] < bv || (swv[w] == bv && swi[w] < bi)) { bv = swv[w]; bi = swi[w]; }
            g_idx[(size_t)bn * KNB + sel] = bi;
            swinner = bi;
        }
        __syncthreads();
        if (idr[0] == swinner) {
            #pragma unroll
            for (int s = 0; s < 7; s++) { vr[s] = vr[s+1]; idr[s] = idr[s+1]; }
            vr[7] = FLT_MAX; idr[7] = 0x7fffffff;
        }
    }
}

// ---------------- stats infra ----------------
__global__ void zero_all_stats()
{
    int i = blockIdx.x * 256 + threadIdx.x;
    if (i < 8 * HID) { ((double*)g_dsum)[i] = 0.0; ((double*)g_dsum2)[i] = 0.0; }
}

__global__ void stats_finalize_fold(const float* __restrict__ gamma, const float* __restrict__ beta,
                                    int M, int D, int stage)
{
    int d = blockIdx.x * blockDim.x + threadIdx.x;
    if (d < D) {
        double m = g_dsum[stage][d] / (double)M;
        double v = g_dsum2[stage][d] / (double)M - m * m;
        if (v < 0.0) v = 0.0;
        float a = gamma[d] * rsqrtf((float)v + EPSB);
        g_afa[stage][d] = a;
        g_afc[stage][d] = beta[d] - (float)m * a;
    }
}

// merged finalize for Q/K/V (stages 0,1,2, D=C_, M=M1)
__global__ void stats_finalize_fold3(const float* gq, const float* bq,
                                     const float* gk, const float* bk,
                                     const float* gv, const float* bv)
{
    int i = blockIdx.x * blockDim.x + threadIdx.x;   // 3*C_ threads
    if (i < 3 * C_) {
        int stage = i >> 8;      // /C_
        int d = i & (C_ - 1);
        const float* gamma = stage == 0 ? gq : stage == 1 ? gk : gv;
        const float* beta  = stage == 0 ? bq : stage == 1 ? bk : bv;
        double m = g_dsum[stage][d] / (double)M1;
        double v = g_dsum2[stage][d] / (double)M1 - m * m;
        if (v < 0.0) v = 0.0;
        float a = gamma[d] * rsqrtf((float)v + EPSB);
        g_afa[stage][d] = a;
        g_afc[stage][d] = beta[d] - (float)m * a;
    }
}

// ---------------- posb_raw stats: val = P[jg,d] - P[bn,d] over all (bn,k) ----------------
__global__ __launch_bounds__(256)
void pbstats_kernel(const float* __restrict__ P)
{
    int d = threadIdx.x;
    int rows = M2 / gridDim.x;
    int r0 = blockIdx.x * rows;
    float s = 0.f, s2 = 0.f;
    for (int r = r0; r < r0 + rows; r++) {
        int bn = r >> 5;
        int b  = r >> 16;
        int jg = (b << 11) + g_idx[r];
        float val = P[(size_t)jg * C_ + d] - P[(size_t)bn * C_ + d];
        s += val; s2 += val * val;
    }
    atomicAdd(&g_dsum[ST_PB][d],  (double)s);
    atomicAdd(&g_dsum2[ST_PB][d], (double)s2);
}

// ---------------- BN apply ----------------
__global__ void bn_leaky_apply3(const float* __restrict__ Y, float* __restrict__ out)
{
    size_t e = (size_t)blockIdx.x * blockDim.x + threadIdx.x;
    const size_t total = (size_t)3 * M1 * C_;
    if (e < total) {
        int d = (int)(e & (C_ - 1));
        int stage = ST_Q + (int)(e >> 20);
        float z = g_afa[stage][d] * Y[e] + g_afc[stage][d];
        out[e] = lrelu(z);
    }
}

__global__ void bn_silu_res_apply(const float* __restrict__ Y, const float* __restrict__ res,
                                  float* __restrict__ out)
{
    size_t e = (size_t)blockIdx.x * blockDim.x + threadIdx.x;
    const size_t total = (size_t)M1 * C_;
    if (e < total) {
        int d = (int)(e & (C_ - 1));
        float z = g_afa[ST_M2][d] * Y[e] + g_afc[ST_M2][d];
        out[e] = res[e] + z / (1.f + expf(-z));
    }
}

// ---------------- vec1: s1_raw = vecin @ We1^T, gather-fused A, FMA2, fused stats ----------------
__global__ __launch_bounds__(256)
void vec1_kernel(const float* __restrict__ qb, const float* __restrict__ kb,
                 const float* __restrict__ P,  const float* __restrict__ We1,
                 float* __restrict__ s1)
{
    __shared__ __align__(16) float As[16][128];
    __shared__ __align__(16) float Wsd[16][64];
    __shared__ int sj[128];
    __shared__ float cs[8][32], cs2[8][32];
    int tid = threadIdx.x;
    int m0 = blockIdx.x * 128;
    if (tid < 128) sj[tid] = g_idx[m0 + tid];
    __syncthreads();

    int tx = tid & 15, ty = tid >> 4;
    int lr = tid >> 2;
    int lc = (tid & 3) << 2;
    int r0 = m0 + lr,      bn0 = r0 >> 5, b0 = r0 >> 16;
    int r1 = m0 + lr + 64, bn1 = r1 >> 5, b1 = r1 >> 16;
    int jg0 = (b0 << 11) + sj[lr];
    int jg1 = (b1 << 11) + sj[lr + 64];
    ull acc[4][2] = {};

    for (int k0 = 0; k0 < C_; k0 += 16) {
        #pragma unroll
        for (int h = 0; h < 2; h++) {
            int jg = h ? jg1 : jg0;
            int bn = h ? bn1 : bn0;
            int rr = h ? lr + 64 : lr;
            float4 kf = *(const float4*)&kb[(size_t)jg * C_ + k0 + lc];
            float4 qf = *(const float4*)&qb[(size_t)bn * C_ + k0 + lc];
            float4 pj = *(const float4*)&P [(size_t)jg * C_ + k0 + lc];
            float4 pn = *(const float4*)&P [(size_t)bn * C_ + k0 + lc];
            float4 pa = *(const float4*)&g_afa[ST_PB][k0 + lc];
            float4 pc = *(const float4*)&g_afc[ST_PB][k0 + lc];
            As[lc+0][rr] = kf.x - qf.x + lrelu(pa.x * (pj.x - pn.x) + pc.x);
            As[lc+1][rr] = kf.y - qf.y + lrelu(pa.y * (pj.y - pn.y) + pc.y);
            As[lc+2][rr] = kf.z - qf.z + lrelu(pa.z * (pj.z - pn.z) + pc.z);
            As[lc+3][rr] = kf.w - qf.w + lrelu(pa.w * (pj.w - pn.w) + pc.w);
        }
        {
            int i0 = tid;
            *(ull*)&Wsd[i0 >> 5][2*(i0 & 31)] = dup2(We1[(size_t)(i0 & 31) * C_ + k0 + (i0 >> 5)]);
            int i1 = tid + 256;
            *(ull*)&Wsd[i1 >> 5][2*(i1 & 31)] = dup2(We1[(size_t)(i1 & 31) * C_ + k0 + (i1 >> 5)]);
        }
        __syncthreads();
        #pragma unroll
        for (int kk = 0; kk < 16; kk++) {
            ulonglong2 aA = *(const ulonglong2*)&As[kk][ty*8];
            ulonglong2 aB = *(const ulonglong2*)&As[kk][ty*8 + 4];
            ull ap[4] = { aA.x, aA.y, aB.x, aB.y };
            ulonglong2 wv = *(const ulonglong2*)&Wsd[kk][4*tx];
            #pragma unroll
            for (int i2 = 0; i2 < 4; i2++) {
                fma2(acc[i2][0], ap[i2], wv.x);
                fma2(acc[i2][1], ap[i2], wv.y);
            }
        }
        __syncthreads();
    }
    #pragma unroll
    for (int i2 = 0; i2 < 4; i2++) {
        float2 p0 = unpk(acc[i2][0]), p1 = unpk(acc[i2][1]);
        size_t w0 = (size_t)(m0 + ty*8 + 2*i2) * CPH + tx*2;
        s1[w0]           = p0.x; s1[w0 + 1]       = p1.x;
        s1[w0 + CPH]     = p0.y; s1[w0 + CPH + 1] = p1.y;
    }
    float ps[2], ps2[2];
    #pragma unroll
    for (int j = 0; j < 2; j++) {
        ull s = add2(add2(acc[0][j], acc[1][j]), add2(acc[2][j], acc[3][j]));
        ull q = add2(add2(mul2(acc[0][j], acc[0][j]), mul2(acc[1][j], acc[1][j])),
                     add2(mul2(acc[2][j], acc[2][j]), mul2(acc[3][j], acc[3][j])));
        float2 fs = unpk(s), fq = unpk(q);
        ps[j] = fs.x + fs.y; ps2[j] = fq.x + fq.y;
    }
    ps[0]  += __shfl_down_sync(0xffffffffu, ps[0], 16);
    ps[1]  += __shfl_down_sync(0xffffffffu, ps[1], 16);
    ps2[0] += __shfl_down_sync(0xffffffffu, ps2[0], 16);
    ps2[1] += __shfl_down_sync(0xffffffffu, ps2[1], 16);
    int lane = tid & 31, wrp = tid >> 5;
    if (lane < 16) {
        cs[wrp][tx*2]      = ps[0];  cs[wrp][tx*2 + 1]  = ps[1];
        cs2[wrp][tx*2]     = ps2[0]; cs2[wrp][tx*2 + 1] = ps2[1];
    }
    __syncthreads();
    if (tid < 32) {
        double s = 0.0, s2 = 0.0;
        #pragma unroll
        for (int w = 0; w < 8; w++) { s += cs[w][tid]; s2 += cs2[w][tid]; }
        atomicAdd(&g_dsum[ST_S1][tid], s);
        atomicAdd(&g_dsum2[ST_S1][tid], s2);
    }
}

// ---------------- vec2: s2_raw = leaky(bn(s1)) @ We2^T, FMA2, fused stats ----------------
__global__ __launch_bounds__(256)
void vec2_kernel(const float* __restrict__ s1, const float* __restrict__ We2,
                 float* __restrict__ s2)
{
    __shared__ __align__(16) float As[16][128];
    __shared__ __align__(16) float Wsd[16][64];
    __shared__ float cs[8][32], cs2[8][32];
    int tid = threadIdx.x;
    int m0 = blockIdx.x * 128;
    int tx = tid & 15, ty = tid >> 4;
    int lr = tid >> 2;
    int lc = (tid & 3) << 2;
    ull acc[4][2] = {};

    for (int k0 = 0; k0 < CPH; k0 += 16) {
        #pragma unroll
        for (int h = 0; h < 2; h++) {
            int rr = h ? lr + 64 : lr;
            float4 y  = *(const float4*)&s1[(size_t)(m0 + rr) * CPH + k0 + lc];
            float4 aa = *(const float4*)&g_afa[ST_S1][k0 + lc];
            float4 cc = *(const float4*)&g_afc[ST_S1][k0 + lc];
            As[lc+0][rr] = lrelu(aa.x * y.x + cc.x);
            As[lc+1][rr] = lrelu(aa.y * y.y + cc.y);
            As[lc+2][rr] = lrelu(aa.z * y.z + cc.z);
            As[lc+3][rr] = lrelu(aa.w * y.w + cc.w);
        }
        {
            int i0 = tid;
            *(ull*)&Wsd[i0 >> 5][2*(i0 & 31)] = dup2(We2[(size_t)(i0 & 31) * CPH + k0 + (i0 >> 5)]);
            int i1 = tid + 256;
            *(ull*)&Wsd[i1 >> 5][2*(i1 & 31)] = dup2(We2[(size_t)(i1 & 31) * CPH + k0 + (i1 >> 5)]);
        }
        __syncthreads();
        #pragma unroll
        for (int kk = 0; kk < 16; kk++) {
            ulonglong2 aA = *(const ulonglong2*)&As[kk][ty*8];
            ulonglong2 aB = *(const ulonglong2*)&As[kk][ty*8 + 4];
            ull ap[4] = { aA.x, aA.y, aB.x, aB.y };
            ulonglong2 wv = *(const ulonglong2*)&Wsd[kk][4*tx];
            #pragma unroll
            for (int i2 = 0; i2 < 4; i2++) {
                fma2(acc[i2][0], ap[i2], wv.x);
                fma2(acc[i2][1], ap[i2], wv.y);
            }
        }
        __syncthreads();
    }
    #pragma unroll
    for (int i2 = 0; i2 < 4; i2++) {
        float2 p0 = unpk(acc[i2][0]), p1 = unpk(acc[i2][1]);
        size_t w0 = (size_t)(m0 + ty*8 + 2*i2) * CPH + tx*2;
        s2[w0]           = p0.x; s2[w0 + 1]       = p1.x;
        s2[w0 + CPH]     = p0.y; s2[w0 + CPH + 1] = p1.y;
    }
    float ps[2], ps2[2];
    #pragma unroll
    for (int j = 0; j < 2; j++) {
        ull s = add2(add2(acc[0][j], acc[1][j]), add2(acc[2][j], acc[3][j]));
        ull q = add2(add2(mul2(acc[0][j], acc[0][j]), mul2(acc[1][j], acc[1][j])),
                     add2(mul2(acc[2][j], acc[2][j]), mul2(acc[3][j], acc[3][j])));
        float2 fs = unpk(s), fq = unpk(q);
        ps[j] = fs.x + fs.y; ps2[j] = fq.x + fq.y;
    }
    ps[0]  += __shfl_down_sync(0xffffffffu, ps[0], 16);
    ps[1]  += __shfl_down_sync(0xffffffffu, ps[1], 16);
    ps2[0] += __shfl_down_sync(0xffffffffu, ps2[0], 16);
    ps2[1] += __shfl_down_sync(0xffffffffu, ps2[1], 16);
    int lane = tid & 31, wrp = tid >> 5;
    if (lane < 16) {
        cs[wrp][tx*2]      = ps[0];  cs[wrp][tx*2 + 1]  = ps[1];
        cs2[wrp][tx*2]     = ps2[0]; cs2[wrp][tx*2 + 1] = ps2[1];
    }
    __syncthreads();
    if (tid < 32) {
        double s = 0.0, s2 = 0.0;
        #pragma unroll
        for (int w = 0; w < 8; w++) { s += cs[w][tid]; s2 += cs2[w][tid]; }
        atomicAdd(&g_dsum[ST_S2][tid], s);
        atomicAdd(&g_dsum2[ST_S2][tid], s2);
    }
}

// ---------------- attention: BN+leaky(s2) -> softmax over k -> combine + residual ----------------
__global__ __launch_bounds__(256)
void attn_kernel(const float* __restrict__ x, const float* __restrict__ s2,
                 const float* __restrict__ vb, const float* __restrict__ P,
                 float* __restrict__ xattn)
{
    int bn = blockIdx.x;
    int t = threadIdx.x;
    __shared__ float soft[KNB][CPH + 1];
    __shared__ int sj[KNB];
    size_t base = (size_t)bn * KNB * CPH;
    for (int e = t; e < KNB * CPH; e += 256) {
        int g = e & 31;
        float y = s2[base + e];
        soft[e >> 5][g] = lrelu(g_afa[ST_S2][g] * y + g_afc[ST_S2][g]);
    }
    if (t < KNB) sj[t] = g_idx[(size_t)bn * KNB + t];
    __syncthreads();
    if (t < CPH) {
        float mx = -FLT_MAX;
        #pragma unroll
        for (int k = 0; k < KNB; k++) mx = fmaxf(mx, soft[k][t]);
        float s = 0.f;
        #pragma unroll
        for (int k = 0; k < KNB; k++) { float ev = expf(soft[k][t] - mx); soft[k][t] = ev; s += ev; }
        float inv = 1.f / s;
        #pragma unroll
        for (int k = 0; k < KNB; k++) soft[k][t] *= inv;
    }
    __syncthreads();

    int c = t, g = t >> 3;
    int b = bn >> 11;
    float pn = P[(size_t)bn * C_ + c];
    float pa = g_afa[ST_PB][c], pc = g_afc[ST_PB][c];
    float acc = 0.f;
    #pragma unroll
    for (int k = 0; k < KNB; k++) {
        int jg = (b << 11) + sj[k];
        float posb = lrelu(pa * (P[(size_t)jg * C_ + c] - pn) + pc);
        acc += (vb[(size_t)jg * C_ + c] + posb) * soft[k][g];
    }
    size_t o = (size_t)bn * C_ + c;
    xattn[o] = x[o] + acc;
}

extern "C" void kernel_launch(void* const* d_in, const int* in_sizes, int n_in,
                              void* d_out, int out_size)
{
    const float* x   = (const float*)d_in[0];
    const float* pos = (const float*)d_in[1];
    const float* Wq  = (const float*)d_in[2];
    const float* gq  = (const float*)d_in[3];
    const float* bq  = (const float*)d_in[4];
    const float* Wk  = (const float*)d_in[5];
    const float* gk  = (const float*)d_in[6];
    const float* bk  = (const float*)d_in[7];
    const float* Wv  = (const float*)d_in[8];
    const float* gv  = (const float*)d_in[9];
    const float* bv  = (const float*)d_in[10];
    const float* Wpb = (const float*)d_in[11];
    const float* gpb = (const float*)d_in[12];
    const float* bpb = (const float*)d_in[13];
    const float* We1 = (const float*)d_in[14];
    const float* ge1 = (const float*)d_in[15];
    const float* be1 = (const float*)d_in[16];
    const float* We2 = (const float*)d_in[17];
    const float* ge2 = (const float*)d_in[18];
    const float* be2 = (const float*)d_in[19];
    const float* Wm1 = (const float*)d_in[20];
    const float* gm1 = (const float*)d_in[21];
    const float* bm1 = (const float*)d_in[22];
    const float* Wm2 = (const float*)d_in[23];
    const float* gm2 = (const float*)d_in[24];
    const float* bm2 = (const float*)d_in[25];
    float* out = (float*)d_out;

    void* p;
    float *qkv, *tmp, *sqv, *dist, *s1, *s2, *xatt;
    cudaGetSymbolAddress(&p, g_qkv);   qkv  = (float*)p;
    cudaGetSymbolAddress(&p, g_tmp4);  tmp  = (float*)p;
    cudaGetSymbolAddress(&p, g_sqv);   sqv  = (float*)p;
    cudaGetSymbolAddress(&p, g_dist);  dist = (float*)p;
    cudaGetSymbolAddress(&p, g_s1);    s1   = (float*)p;
    cudaGetSymbolAddress(&p, g_s2);    s2   = (float*)p;
    cudaGetSymbolAddress(&p, g_xattn); xatt = (float*)p;

    const size_t SL = (size_t)M1 * C_;
    float* t0 = tmp;
    float* t1 = tmp + SL;
    float* t2 = tmp + 2*SL;
    float* t3 = tmp + 3*SL;
    float* qb = qkv;
    float* kb = qkv + SL;
    float* vb = qkv + 2*SL;

    const int BLK = 256;

    // 1. zero stats
    zero_all_stats<<<16, 256>>>();

    // 2. batched GEMM: q,k,v raw (stats fused) + P
    {
        Gemm4 g = { { x, x, x, pos }, { Wq, Wk, Wv, Wpb }, { t0, t1, t2, t3 },
                    { ST_Q, ST_K, ST_V, -1 } };
        gemm128_kernel<<<dim3(C_/128, M1/128, 4), 256>>>(g, C_, C_, 0);
    }
    // 3. merged finalize q/k/v
    stats_finalize_fold3<<<3, 256>>>(gq, bq, gk, bk, gv, bv);
    // 4. BN apply
    bn_leaky_apply3<<<(int)((3*SL + BLK - 1) / BLK), BLK>>>(tmp, qkv);
    // 5. sq
    sq_kernel<<<(M1 * 32 + BLK - 1) / BLK, BLK>>>(kb, sqv);
    // 6. dist  (lands in the ncu -s 5 -c 1 capture window)
    dist_kernel<<<dim3(NPTS/128, NPTS/128, B_), 256>>>(kb, sqv, dist);
    // 7. topk
    topk_kernel<<<M1, 256>>>(dist);
    // 8-9. posb stats
    pbstats_kernel<<<256, 256>>>(t3);
    stats_finalize_fold<<<1, 256>>>(gpb, bpb, M2, C_, ST_PB);
    // 10-13. vector path
    vec1_kernel<<<M2/128, 256>>>(qb, kb, t3, We1, s1);
    stats_finalize_fold<<<1, 256>>>(ge1, be1, M2, CPH, ST_S1);
    vec2_kernel<<<M2/128, 256>>>(s1, We2, s2);
    stats_finalize_fold<<<1, 256>>>(ge2, be2, M2, CPH, ST_S2);
    // 14. attention + residual
    attn_kernel<<<M1, 256>>>(x, s2, vb, t3, xatt);
    // 15-19. MLP
    {
        Gemm4 g = { { xatt, 0, 0, 0 }, { Wm1, 0, 0, 0 }, { t0, 0, 0, 0 },
                    { ST_M1, -1, -1, -1 } };
        gemm128_kernel<<<dim3(HID/128, M1/128, 1), 256>>>(g, HID, C_, 0);
    }
    stats_finalize_fold<<<2, 256>>>(gm1, bm1, M1, HID, ST_M1);
    {
        Gemm4 g = { { t0, 0, 0, 0 }, { Wm2, 0, 0, 0 }, { t2, 0, 0, 0 },
                    { ST_M2, -1, -1, -1 } };
        gemm128_kernel<<<dim3(C_/128, M1/128, 1), 256>>>(g, C_, HID, 1);
    }
    stats_finalize_fold<<<1, 256>>>(gm2, bm2, M1, C_, ST_M2);
    bn_silu_res_apply<<<(int)((SL + BLK - 1) / BLK), BLK>>>(t2, xatt, out);
}

// round 7
// speedup vs baseline: 3.2036x; 1.0268x over previous
#include <cuda_runtime.h>
#include <math.h>
#include <float.h>

#define B_   2
#define NPTS 2048
#define C_   256
#define KNB  32
#define HID  512
#define CPH  32
#define M1   (B_*NPTS)        // 4096
#define M2   (B_*NPTS*KNB)    // 131072
#define EPSB 1e-5f

#define ST_Q  0
#define ST_K  1
#define ST_V  2
#define ST_PB 3
#define ST_S1 4
#define ST_S2 5
#define ST_M1 6
#define ST_M2 7

#define INV_M1 (1.0/4096.0)     // exact power of 2
#define INV_M2 (1.0/131072.0)   // exact power of 2

typedef unsigned long long ull;

// ---------------- device scratch ----------------
__device__ float g_qkv[3*M1*C_];               // q, k, v (BN applied)
__device__ float g_tmp4[(size_t)M1*C_*4];      // raw q,k,v + P; reused for MLP raws
__device__ float g_sqv[M1];
__device__ float g_dist[(size_t)B_*NPTS*NPTS];
__device__ int   g_idx[M2];
__device__ float g_s1[(size_t)M2*CPH];
__device__ float g_s2[(size_t)M2*CPH];
__device__ float g_xattn[M1*C_];
__device__ double g_dsum[8][HID];
__device__ double g_dsum2[8][HID];

__device__ __forceinline__ float lrelu(float z) { return z >= 0.f ? z : 0.2f * z; }

// fold coefficients from accumulated stats (deterministic across all callers)
__device__ __forceinline__ void foldco(int stage, int d, double invM,
                                       const float* __restrict__ gamma,
                                       const float* __restrict__ beta,
                                       float& a, float& c)
{
    double m = g_dsum[stage][d] * invM;
    double v = g_dsum2[stage][d] * invM - m * m;
    if (v < 0.0) v = 0.0;
    a = gamma[d] * rsqrtf((float)v + EPSB);
    c = beta[d] - (float)m * a;
}

// ---------------- packed f32x2 helpers ----------------
__device__ __forceinline__ void fma2(ull& d, ull a, ull b) {
    asm("fma.rn.f32x2 %0, %1, %2, %0;" : "+l"(d) : "l"(a), "l"(b));
}
__device__ __forceinline__ ull add2(ull a, ull b) {
    ull d; asm("add.rn.f32x2 %0, %1, %2;" : "=l"(d) : "l"(a), "l"(b)); return d;
}
__device__ __forceinline__ ull mul2(ull a, ull b) {
    ull d; asm("mul.rn.f32x2 %0, %1, %2;" : "=l"(d) : "l"(a), "l"(b)); return d;
}
__device__ __forceinline__ ull dup2(float x) {
    ull r; asm("mov.b64 %0, {%1, %1};" : "=l"(r) : "f"(x)); return r;
}
__device__ __forceinline__ float2 unpk(ull v) {
    float2 f; asm("mov.b64 {%0, %1}, %2;" : "=f"(f.x), "=f"(f.y) : "l"(v)); return f;
}

// XOR swizzle for the duplicated-W tile
__device__ __forceinline__ int swzW(int f) {
    int p = f >> 2;
    return (((p ^ ((p >> 3) & 7)) << 2) | (f & 3));
}

// ---------------- batched TN GEMM, FMA2, fused stats, optional silu(bn) on A ----------------
struct Gemm4 {
    const float* A[4];
    const float* W[4];
    float*       C[4];
    int          stage[4];   // -1 = no stats
};

__global__ __launch_bounds__(256)
void gemm128_kernel(Gemm4 g, int N, int K, int dosilu,
                    const float* __restrict__ fg, const float* __restrict__ fb)
{
    __shared__ __align__(16) float As[16][128];
    __shared__ __align__(16) float Wd[16][256];
    __shared__ float sfa[HID], sfc[HID];
    int z = blockIdx.z;
    const float* A = g.A[z];
    const float* W = g.W[z];
    float*       C = g.C[z];
    int stage = g.stage[z];
    int tid = threadIdx.x;

    if (dosilu) {
        for (int d = tid; d < K; d += 256)
            foldco(ST_M1, d, INV_M1, fg, fb, sfa[d], sfc[d]);
        __syncthreads();
    }

    int tx = tid & 15, ty = tid >> 4;
    int m0 = blockIdx.y * 128, n0 = blockIdx.x * 128;
    int lr = tid >> 2;
    int lc = (tid & 3) << 2;
    ull acc[4][8] = {};

    int wq0 = swzW(2*lr);
    int wq1 = swzW(2*(lr+64));
    int rq0 = swzW(16*tx);
    int rq1 = swzW(16*tx + 4);
    int rq2 = swzW(16*tx + 8);
    int rq3 = swzW(16*tx + 12);

    for (int k0 = 0; k0 < K; k0 += 16) {
        float4 a0 = *(const float4*)&A[(size_t)(m0 + lr)      * K + k0 + lc];
        float4 a1 = *(const float4*)&A[(size_t)(m0 + lr + 64) * K + k0 + lc];
        if (dosilu) {
            #pragma unroll
            for (int i = 0; i < 4; i++) {
                float aa = sfa[k0 + lc + i];
                float cc = sfc[k0 + lc + i];
                float* pz = (i==0)?&a0.x:(i==1)?&a0.y:(i==2)?&a0.z:&a0.w;
                float* pw = (i==0)?&a1.x:(i==1)?&a1.y:(i==2)?&a1.z:&a1.w;
                float z0 = aa * (*pz) + cc; *pz = z0 / (1.f + __expf(-z0));
                float z1 = aa * (*pw) + cc; *pw = z1 / (1.f + __expf(-z1));
            }
        }
        float4 w0 = *(const float4*)&W[(size_t)(n0 + lr)      * K + k0 + lc];
        float4 w1 = *(const float4*)&W[(size_t)(n0 + lr + 64) * K + k0 + lc];
        As[lc+0][lr] = a0.x; As[lc+1][lr] = a0.y; As[lc+2][lr] = a0.z; As[lc+3][lr] = a0.w;
        As[lc+0][lr+64] = a1.x; As[lc+1][lr+64] = a1.y; As[lc+2][lr+64] = a1.z; As[lc+3][lr+64] = a1.w;
        *(ull*)&Wd[lc+0][wq0] = dup2(w0.x);
        *(ull*)&Wd[lc+1][wq0] = dup2(w0.y);
        *(ull*)&Wd[lc+2][wq0] = dup2(w0.z);
        *(ull*)&Wd[lc+3][wq0] = dup2(w0.w);
        *(ull*)&Wd[lc+0][wq1] = dup2(w1.x);
        *(ull*)&Wd[lc+1][wq1] = dup2(w1.y);
        *(ull*)&Wd[lc+2][wq1] = dup2(w1.z);
        *(ull*)&Wd[lc+3][wq1] = dup2(w1.w);
        __syncthreads();
        #pragma unroll
        for (int kk = 0; kk < 16; kk++) {
            ulonglong2 aA = *(const ulonglong2*)&As[kk][ty*8];
            ulonglong2 aB = *(const ulonglong2*)&As[kk][ty*8 + 4];
            ull ap[4] = { aA.x, aA.y, aB.x, aB.y };
            ulonglong2 v0 = *(const ulonglong2*)&Wd[kk][rq0];
            ulonglong2 v1 = *(const ulonglong2*)&Wd[kk][rq1];
            ulonglong2 v2 = *(const ulonglong2*)&Wd[kk][rq2];
            ulonglong2 v3 = *(const ulonglong2*)&Wd[kk][rq3];
            ull wp[8] = { v0.x, v0.y, v1.x, v1.y, v2.x, v2.y, v3.x, v3.y };
            #pragma unroll
            for (int i2 = 0; i2 < 4; i2++)
                #pragma unroll
                for (int j = 0; j < 8; j++)
                    fma2(acc[i2][j], ap[i2], wp[j]);
        }
        __syncthreads();
    }

    #pragma unroll
    for (int i2 = 0; i2 < 4; i2++) {
        float2 p[8];
        #pragma unroll
        for (int j = 0; j < 8; j++) p[j] = unpk(acc[i2][j]);
        size_t r0 = (size_t)(m0 + ty*8 + 2*i2) * N + n0 + tx*8;
        size_t r1 = r0 + N;
        *(float4*)&C[r0]     = make_float4(p[0].x, p[1].x, p[2].x, p[3].x);
        *(float4*)&C[r0 + 4] = make_float4(p[4].x, p[5].x, p[6].x, p[7].x);
        *(float4*)&C[r1]     = make_float4(p[0].y, p[1].y, p[2].y, p[3].y);
        *(float4*)&C[r1 + 4] = make_float4(p[4].y, p[5].y, p[6].y, p[7].y);
    }

    if (stage >= 0) {
        float ps[8], ps2[8];
        #pragma unroll
        for (int j = 0; j < 8; j++) {
            ull s = add2(add2(acc[0][j], acc[1][j]), add2(acc[2][j], acc[3][j]));
            ull q = add2(add2(mul2(acc[0][j], acc[0][j]), mul2(acc[1][j], acc[1][j])),
                         add2(mul2(acc[2][j], acc[2][j]), mul2(acc[3][j], acc[3][j])));
            float2 fs = unpk(s), fq = unpk(q);
            ps[j]  = fs.x + fs.y;
            ps2[j] = fq.x + fq.y;
        }
        #pragma unroll
        for (int j = 0; j < 8; j++) {
            ps[j]  += __shfl_down_sync(0xffffffffu, ps[j], 16);
            ps2[j] += __shfl_down_sync(0xffffffffu, ps2[j], 16);
        }
        int lane = tid & 31, wrp = tid >> 5;
        if (lane < 16) {
            #pragma unroll
            for (int j = 0; j < 8; j++) {
                As[wrp][tx*8 + j]     = ps[j];
                As[wrp + 8][tx*8 + j] = ps2[j];
            }
        }
        __syncthreads();
        if (tid < 128) {
            double s = 0.0, s2 = 0.0;
            #pragma unroll
            for (int w = 0; w < 8; w++) { s += As[w][tid]; s2 += As[w + 8][tid]; }
            atomicAdd(&g_dsum[stage][n0 + tid], s);
            atomicAdd(&g_dsum2[stage][n0 + tid], s2);
        }
    }
}

// ---------------- BN apply for q/k/v raws + fused sq (row sum of key^2) ----------------
// grid = 3*4096 blocks, 256 threads; block = one (slice,row)
__global__ __launch_bounds__(256)
void bnqkv_kernel(const float* __restrict__ Y, float* __restrict__ out,
                  const float* __restrict__ gq, const float* __restrict__ bq,
                  const float* __restrict__ gk, const float* __restrict__ bk,
                  const float* __restrict__ gv, const float* __restrict__ bv,
                  float* __restrict__ sqv)
{
    int blk = blockIdx.x;
    int slice = blk >> 12;          // 4096 rows per slice
    int row   = blk & 4095;
    int d = threadIdx.x;
    const float* gamma = slice == 0 ? gq : slice == 1 ? gk : gv;
    const float* beta  = slice == 0 ? bq : slice == 1 ? bk : bv;
    float a, c;
    foldco(slice, d, INV_M1, gamma, beta, a, c);
    size_t e = (size_t)blk * 256 + d;
    float z = a * Y[e] + c;
    float o = lrelu(z);
    out[e] = o;

    if (slice == 1) {
        __shared__ float sh[8];
        float s = o * o;
        #pragma unroll
        for (int off = 16; off; off >>= 1) s += __shfl_down_sync(0xffffffffu, s, off);
        if ((d & 31) == 0) sh[d >> 5] = s;
        __syncthreads();
        if (d == 0) {
            float t = 0.f;
            #pragma unroll
            for (int w = 0; w < 8; w++) t += sh[w];
            sqv[row] = t;
        }
    }
}

// ---------------- symmetric dist: triangle tiles, write both orientations ----------------
__global__ __launch_bounds__(256)
void dist_kernel(const float* __restrict__ key, const float* __restrict__ sq,
                 float* __restrict__ dist)
{
    int b = blockIdx.z;
    const float* A  = key + (size_t)b * NPTS * C_;
    const float* sb = sq + b * NPTS;
    float* D = dist + (size_t)b * NPTS * NPTS;

    // unrank triangle: blockIdx.x in [0,136) -> (bi, bj), bi <= bj
    int t = blockIdx.x, bi = 0;
    while (t >= 16 - bi) { t -= 16 - bi; bi++; }
    int bj = bi + t;

    __shared__ __align__(16) float As[16][128];
    __shared__ __align__(16) float Wd[16][256];
    int tid = threadIdx.x;
    int tx = tid & 15, ty = tid >> 4;
    int m0 = bi * 128, n0 = bj * 128;
    int lr = tid >> 2;
    int lc = (tid & 3) << 2;
    ull acc[4][8] = {};

    int wq0 = swzW(2*lr);
    int wq1 = swzW(2*(lr+64));
    int rq0 = swzW(16*tx);
    int rq1 = swzW(16*tx + 4);
    int rq2 = swzW(16*tx + 8);
    int rq3 = swzW(16*tx + 12);

    for (int k0 = 0; k0 < C_; k0 += 16) {
        float4 a0 = *(const float4*)&A[(size_t)(m0 + lr)      * C_ + k0 + lc];
        float4 a1 = *(const float4*)&A[(size_t)(m0 + lr + 64) * C_ + k0 + lc];
        float4 w0 = *(const float4*)&A[(size_t)(n0 + lr)      * C_ + k0 + lc];
        float4 w1 = *(const float4*)&A[(size_t)(n0 + lr + 64) * C_ + k0 + lc];
        As[lc+0][lr] = a0.x; As[lc+1][lr] = a0.y; As[lc+2][lr] = a0.z; As[lc+3][lr] = a0.w;
        As[lc+0][lr+64] = a1.x; As[lc+1][lr+64] = a1.y; As[lc+2][lr+64] = a1.z; As[lc+3][lr+64] = a1.w;
        *(ull*)&Wd[lc+0][wq0] = dup2(w0.x);
        *(ull*)&Wd[lc+1][wq0] = dup2(w0.y);
        *(ull*)&Wd[lc+2][wq0] = dup2(w0.z);
        *(ull*)&Wd[lc+3][wq0] = dup2(w0.w);
        *(ull*)&Wd[lc+0][wq1] = dup2(w1.x);
        *(ull*)&Wd[lc+1][wq1] = dup2(w1.y);
        *(ull*)&Wd[lc+2][wq1] = dup2(w1.z);
        *(ull*)&Wd[lc+3][wq1] = dup2(w1.w);
        __syncthreads();
        #pragma unroll
        for (int kk = 0; kk < 16; kk++) {
            ulonglong2 aA = *(const ulonglong2*)&As[kk][ty*8];
            ulonglong2 aB = *(const ulonglong2*)&As[kk][ty*8 + 4];
            ull ap[4] = { aA.x, aA.y, aB.x, aB.y };
            ulonglong2 v0 = *(const ulonglong2*)&Wd[kk][rq0];
            ulonglong2 v1 = *(const ulonglong2*)&Wd[kk][rq1];
            ulonglong2 v2 = *(const ulonglong2*)&Wd[kk][rq2];
            ulonglong2 v3 = *(const ulonglong2*)&Wd[kk][rq3];
            ull wp[8] = { v0.x, v0.y, v1.x, v1.y, v2.x, v2.y, v3.x, v3.y };
            #pragma unroll
            for (int i2 = 0; i2 < 4; i2++)
                #pragma unroll
                for (int j = 0; j < 8; j++)
                    fma2(acc[i2][j], ap[i2], wp[j]);
        }
        __syncthreads();
    }
    float sn[8], sm[8];
    *(float4*)(sn)     = *(const float4*)&sb[n0 + tx*8];
    *(float4*)(sn + 4) = *(const float4*)&sb[n0 + tx*8 + 4];
    *(float4*)(sm)     = *(const float4*)&sb[m0 + ty*8];
    *(float4*)(sm + 4) = *(const float4*)&sb[m0 + ty*8 + 4];

    // normal orientation
    #pragma unroll
    for (int i2 = 0; i2 < 4; i2++) {
        float sm0 = sm[2*i2], sm1 = sm[2*i2 + 1];
        float o0[8], o1[8];
        #pragma unroll
        for (int j = 0; j < 8; j++) {
            float2 p = unpk(acc[i2][j]);
            o0[j] = sm0 + sn[j] - 2.f * p.x;
            o1[j] = sm1 + sn[j] - 2.f * p.y;
        }
        size_t r0 = (size_t)(m0 + ty*8 + 2*i2) * NPTS + n0 + tx*8;
        *(float4*)&D[r0]            = *(float4*)(o0);
        *(float4*)&D[r0 + 4]        = *(float4*)(o0 + 4);
        *(float4*)&D[r0 + NPTS]     = *(float4*)(o1);
        *(float4*)&D[r0 + NPTS + 4] = *(float4*)(o1 + 4);
    }
    // mirrored orientation for off-diagonal tiles
    if (bi != bj) {
        #pragma unroll
        for (int j = 0; j < 8; j++) {
            float snj = sn[j];
            float o[8];
            #pragma unroll
            for (int i2 = 0; i2 < 4; i2++) {
                float2 p = unpk(acc[i2][j]);
                o[2*i2]     = snj + sm[2*i2]     - 2.f * p.x;
                o[2*i2 + 1] = snj + sm[2*i2 + 1] - 2.f * p.y;
            }
            size_t r = (size_t)(n0 + tx*8 + j) * NPTS + m0 + ty*8;
            *(float4*)&D[r]     = *(float4*)(o);
            *(float4*)&D[r + 4] = *(float4*)(o + 4);
        }
    }
}

// ---------------- top-32: warp-local barrier-free extraction + single merge ----------------
#define CE(i,j) { if (vr[j] < vr[i] || (vr[j] == vr[i] && idr[j] < idr[i])) { \
                    float tv = vr[i]; vr[i] = vr[j]; vr[j] = tv; \
                    int ti = idr[i]; idr[i] = idr[j]; idr[j] = ti; } }

__global__ __launch_bounds__(256)
void topk_kernel(const float* __restrict__ dist)
{
    int bn = blockIdx.x;
    const float* row = dist + (size_t)bn * NPTS;
    int t = threadIdx.x;
    int lane = t & 31, wrp = t >> 5;

    __shared__ float lv[8][32];
    __shared__ int   li[8][32];

    // phase 1: each warp extracts sorted top-32 of its 256 elements (no block syncs)
    {
        float vr[8]; int idr[8];
        #pragma unroll
        for (int s = 0; s < 8; s++) {
            int j = wrp * 256 + s * 32 + lane;
            vr[s] = row[j]; idr[s] = j;
        }
        CE(0,1) CE(2,3) CE(4,5) CE(6,7)
        CE(0,2) CE(1,3) CE(4,6) CE(5,7)
        CE(1,2) CE(5,6)
        CE(0,4) CE(1,5) CE(2,6) CE(3,7)
        CE(2,4) CE(3,5)
        CE(1,2) CE(3,4) CE(5,6)

        float outv = FLT_MAX; int outi = 0x7fffffff;
        for (int sel = 0; sel < KNB; sel++) {
            float cv = vr[0]; int ci = idr[0];
            int myhead = idr[0];
            #pragma unroll
            for (int o = 16; o; o >>= 1) {
                float ov = __shfl_xor_sync(0xffffffffu, cv, o);
                int   oi = __shfl_xor_sync(0xffffffffu, ci, o);
                if (ov < cv || (ov == cv && oi < ci)) { cv = ov; ci = oi; }
            }
            if (lane == sel) { outv = cv; outi = ci; }
            if (myhead == ci) {
                #pragma unroll
                for (int s = 0; s < 7; s++) { vr[s] = vr[s+1]; idr[s] = idr[s+1]; }
                vr[7] = FLT_MAX; idr[7] = 0x7fffffff;
            }
        }
        lv[wrp][lane] = outv;
        li[wrp][lane] = outi;
    }
    __syncthreads();

    // phase 2: warp 0 merges; lane takes position `lane` of each of the 8 sorted lists
    if (wrp == 0) {
        float vr[8]; int idr[8];
        #pragma unroll
        for (int j = 0; j < 8; j++) { vr[j] = lv[j][lane]; idr[j] = li[j][lane]; }
        CE(0,1) CE(2,3) CE(4,5) CE(6,7)
        CE(0,2) CE(1,3) CE(4,6) CE(5,7)
        CE(1,2) CE(5,6)
        CE(0,4) CE(1,5) CE(2,6) CE(3,7)
        CE(2,4) CE(3,5)
        CE(1,2) CE(3,4) CE(5,6)

        for (int sel = 0; sel < KNB; sel++) {
            float cv = vr[0]; int ci = idr[0];
            int myhead = idr[0];
            #pragma unroll
            for (int o = 16; o; o >>= 1) {
                float ov = __shfl_xor_sync(0xffffffffu, cv, o);
                int   oi = __shfl_xor_sync(0xffffffffu, ci, o);
                if (ov < cv || (ov == cv && oi < ci)) { cv = ov; ci = oi; }
            }
            if (lane == 0) g_idx[(size_t)bn * KNB + sel] = ci;
            if (myhead == ci) {
                #pragma unroll
                for (int s = 0; s < 7; s++) { vr[s] = vr[s+1]; idr[s] = idr[s+1]; }
                vr[7] = FLT_MAX; idr[7] = 0x7fffffff;
            }
        }
    }
}

// ---------------- stats infra ----------------
__global__ void zero_all_stats()
{
    int i = blockIdx.x * 256 + threadIdx.x;
    if (i < 8 * HID) { ((double*)g_dsum)[i] = 0.0; ((double*)g_dsum2)[i] = 0.0; }
}

// ---------------- posb stats via moments: Σ(pj-pn), Σ(pj-pn)^2 ----------------
__global__ __launch_bounds__(256)
void pbstats_kernel(const float* __restrict__ P)
{
    int d = threadIdx.x;
    float s = 0.f, s2 = 0.f;
    for (int gidx = 0; gidx < 16; gidx++) {
        int bn = blockIdx.x * 16 + gidx;
        int b  = bn >> 11;
        float pn = P[(size_t)bn * C_ + d];
        const int* ip = &g_idx[(size_t)bn * KNB];
        float A1 = 0.f, A2 = 0.f;
        #pragma unroll 4
        for (int k = 0; k < KNB; k++) {
            int jg = (b << 11) + ip[k];
            float v = P[(size_t)jg * C_ + d];
            A1 += v; A2 += v * v;
        }
        s  += A1 - 32.f * pn;
        s2 += A2 - 2.f * pn * A1 + 32.f * pn * pn;
    }
    atomicAdd(&g_dsum[ST_PB][d],  (double)s);
    atomicAdd(&g_dsum2[ST_PB][d], (double)s2);
}

// ---------------- final BN+silu+residual (per-thread fold) ----------------
__global__ void bn_silu_res_apply(const float* __restrict__ Y, const float* __restrict__ res,
                                  float* __restrict__ out,
                                  const float* __restrict__ gm2, const float* __restrict__ bm2)
{
    int d = threadIdx.x;
    float a, c;
    foldco(ST_M2, d, INV_M1, gm2, bm2, a, c);
    size_t e = (size_t)blockIdx.x * 256 + d;
    float z = a * Y[e] + c;
    out[e] = res[e] + z / (1.f + expf(-z));
}

// ---------------- vec1: s1_raw = vecin @ We1^T, gather-fused A, FMA2, fused stats ----------------
__global__ __launch_bounds__(256)
void vec1_kernel(const float* __restrict__ qb, const float* __restrict__ kb,
                 const float* __restrict__ P,  const float* __restrict__ We1,
                 const float* __restrict__ gpb, const float* __restrict__ bpb,
                 float* __restrict__ s1)
{
    __shared__ __align__(16) float As[16][128];
    __shared__ __align__(16) float Wsd[16][64];
    __shared__ __align__(16) float spa[C_], spc[C_];
    __shared__ int sj[128];
    __shared__ float cs[8][32], cs2[8][32];
    int tid = threadIdx.x;
    int m0 = blockIdx.x * 128;
    foldco(ST_PB, tid, INV_M2, gpb, bpb, spa[tid], spc[tid]);
    if (tid < 128) sj[tid] = g_idx[m0 + tid];
    __syncthreads();

    int tx = tid & 15, ty = tid >> 4;
    int lr = tid >> 2;
    int lc = (tid & 3) << 2;
    int r0 = m0 + lr,      bn0 = r0 >> 5, b0 = r0 >> 16;
    int r1 = m0 + lr + 64, bn1 = r1 >> 5, b1 = r1 >> 16;
    int jg0 = (b0 << 11) + sj[lr];
    int jg1 = (b1 << 11) + sj[lr + 64];
    ull acc[4][2] = {};

    for (int k0 = 0; k0 < C_; k0 += 16) {
        #pragma unroll
        for (int h = 0; h < 2; h++) {
            int jg = h ? jg1 : jg0;
            int bn = h ? bn1 : bn0;
            int rr = h ? lr + 64 : lr;
            float4 kf = *(const float4*)&kb[(size_t)jg * C_ + k0 + lc];
            float4 qf = *(const float4*)&qb[(size_t)bn * C_ + k0 + lc];
            float4 pj = *(const float4*)&P [(size_t)jg * C_ + k0 + lc];
            float4 pn = *(const float4*)&P [(size_t)bn * C_ + k0 + lc];
            float4 pa = *(const float4*)&spa[k0 + lc];
            float4 pc = *(const float4*)&spc[k0 + lc];
            As[lc+0][rr] = kf.x - qf.x + lrelu(pa.x * (pj.x - pn.x) + pc.x);
            As[lc+1][rr] = kf.y - qf.y + lrelu(pa.y * (pj.y - pn.y) + pc.y);
            As[lc+2][rr] = kf.z - qf.z + lrelu(pa.z * (pj.z - pn.z) + pc.z);
            As[lc+3][rr] = kf.w - qf.w + lrelu(pa.w * (pj.w - pn.w) + pc.w);
        }
        {
            int i0 = tid;
            *(ull*)&Wsd[i0 >> 5][2*(i0 & 31)] = dup2(We1[(size_t)(i0 & 31) * C_ + k0 + (i0 >> 5)]);
            int i1 = tid + 256;
            *(ull*)&Wsd[i1 >> 5][2*(i1 & 31)] = dup2(We1[(size_t)(i1 & 31) * C_ + k0 + (i1 >> 5)]);
        }
        __syncthreads();
        #pragma unroll
        for (int kk = 0; kk < 16; kk++) {
            ulonglong2 aA = *(const ulonglong2*)&As[kk][ty*8];
            ulonglong2 aB = *(const ulonglong2*)&As[kk][ty*8 + 4];
            ull ap[4] = { aA.x, aA.y, aB.x, aB.y };
            ulonglong2 wv = *(const ulonglong2*)&Wsd[kk][4*tx];
            #pragma unroll
            for (int i2 = 0; i2 < 4; i2++) {
                fma2(acc[i2][0], ap[i2], wv.x);
                fma2(acc[i2][1], ap[i2], wv.y);
            }
        }
        __syncthreads();
    }
    #pragma unroll
    for (int i2 = 0; i2 < 4; i2++) {
        float2 p0 = unpk(acc[i2][0]), p1 = unpk(acc[i2][1]);
        size_t w0 = (size_t)(m0 + ty*8 + 2*i2) * CPH + tx*2;
        s1[w0]           = p0.x; s1[w0 + 1]       = p1.x;
        s1[w0 + CPH]     = p0.y; s1[w0 + CPH + 1] = p1.y;
    }
    float ps[2], ps2[2];
    #pragma unroll
    for (int j = 0; j < 2; j++) {
        ull s = add2(add2(acc[0][j], acc[1][j]), add2(acc[2][j], acc[3][j]));
        ull q = add2(add2(mul2(acc[0][j], acc[0][j]), mul2(acc[1][j], acc[1][j])),
                     add2(mul2(acc[2][j], acc[2][j]), mul2(acc[3][j], acc[3][j])));
        float2 fs = unpk(s), fq = unpk(q);
        ps[j] = fs.x + fs.y; ps2[j] = fq.x + fq.y;
    }
    ps[0]  += __shfl_down_sync(0xffffffffu, ps[0], 16);
    ps[1]  += __shfl_down_sync(0xffffffffu, ps[1], 16);
    ps2[0] += __shfl_down_sync(0xffffffffu, ps2[0], 16);
    ps2[1] += __shfl_down_sync(0xffffffffu, ps2[1], 16);
    int lane = tid & 31, wrp = tid >> 5;
    if (lane < 16) {
        cs[wrp][tx*2]      = ps[0];  cs[wrp][tx*2 + 1]  = ps[1];
        cs2[wrp][tx*2]     = ps2[0]; cs2[wrp][tx*2 + 1] = ps2[1];
    }
    __syncthreads();
    if (tid < 32) {
        double s = 0.0, s2 = 0.0;
        #pragma unroll
        for (int w = 0; w < 8; w++) { s += cs[w][tid]; s2 += cs2[w][tid]; }
        atomicAdd(&g_dsum[ST_S1][tid], s);
        atomicAdd(&g_dsum2[ST_S1][tid], s2);
    }
}

// ---------------- vec2: s2_raw = leaky(bn(s1)) @ We2^T, FMA2, fused stats ----------------
__global__ __launch_bounds__(256)
void vec2_kernel(const float* __restrict__ s1, const float* __restrict__ We2,
                 const float* __restrict__ ge1, const float* __restrict__ be1,
                 float* __restrict__ s2)
{
    __shared__ __align__(16) float As[16][128];
    __shared__ __align__(16) float Wsd[16][64];
    __shared__ __align__(16) float sfa[CPH], sfc[CPH];
    __shared__ float cs[8][32], cs2[8][32];
    int tid = threadIdx.x;
    int m0 = blockIdx.x * 128;
    if (tid < CPH) foldco(ST_S1, tid, INV_M2, ge1, be1, sfa[tid], sfc[tid]);
    __syncthreads();

    int tx = tid & 15, ty = tid >> 4;
    int lr = tid >> 2;
    int lc = (tid & 3) << 2;
    ull acc[4][2] = {};

    for (int k0 = 0; k0 < CPH; k0 += 16) {
        #pragma unroll
        for (int h = 0; h < 2; h++) {
            int rr = h ? lr + 64 : lr;
            float4 y  = *(const float4*)&s1[(size_t)(m0 + rr) * CPH + k0 + lc];
            float4 aa = *(const float4*)&sfa[k0 + lc];
            float4 cc = *(const float4*)&sfc[k0 + lc];
            As[lc+0][rr] = lrelu(aa.x * y.x + cc.x);
            As[lc+1][rr] = lrelu(aa.y * y.y + cc.y);
            As[lc+2][rr] = lrelu(aa.z * y.z + cc.z);
            As[lc+3][rr] = lrelu(aa.w * y.w + cc.w);
        }
        {
            int i0 = tid;
            *(ull*)&Wsd[i0 >> 5][2*(i0 & 31)] = dup2(We2[(size_t)(i0 & 31) * CPH + k0 + (i0 >> 5)]);
            int i1 = tid + 256;
            *(ull*)&Wsd[i1 >> 5][2*(i1 & 31)] = dup2(We2[(size_t)(i1 & 31) * CPH + k0 + (i1 >> 5)]);
        }
        __syncthreads();
        #pragma unroll
        for (int kk = 0; kk < 16; kk++) {
            ulonglong2 aA = *(const ulonglong2*)&As[kk][ty*8];
            ulonglong2 aB = *(const ulonglong2*)&As[kk][ty*8 + 4];
            ull ap[4] = { aA.x, aA.y, aB.x, aB.y };
            ulonglong2 wv = *(const ulonglong2*)&Wsd[kk][4*tx];
            #pragma unroll
            for (int i2 = 0; i2 < 4; i2++) {
                fma2(acc[i2][0], ap[i2], wv.x);
                fma2(acc[i2][1], ap[i2], wv.y);
            }
        }
        __syncthreads();
    }
    #pragma unroll
    for (int i2 = 0; i2 < 4; i2++) {
        float2 p0 = unpk(acc[i2][0]), p1 = unpk(acc[i2][1]);
        size_t w0 = (size_t)(m0 + ty*8 + 2*i2) * CPH + tx*2;
        s2[w0]           = p0.x; s2[w0 + 1]       = p1.x;
        s2[w0 + CPH]     = p0.y; s2[w0 + CPH + 1] = p1.y;
    }
    float ps[2], ps2[2];
    #pragma unroll
    for (int j = 0; j < 2; j++) {
        ull s = add2(add2(acc[0][j], acc[1][j]), add2(acc[2][j], acc[3][j]));
        ull q = add2(add2(mul2(acc[0][j], acc[0][j]), mul2(acc[1][j], acc[1][j])),
                     add2(mul2(acc[2][j], acc[2][j]), mul2(acc[3][j], acc[3][j])));
        float2 fs = unpk(s), fq = unpk(q);
        ps[j] = fs.x + fs.y; ps2[j] = fq.x + fq.y;
    }
    ps[0]  += __shfl_down_sync(0xffffffffu, ps[0], 16);
    ps[1]  += __shfl_down_sync(0xffffffffu, ps[1], 16);
    ps2[0] += __shfl_down_sync(0xffffffffu, ps2[0], 16);
    ps2[1] += __shfl_down_sync(0xffffffffu, ps2[1], 16);
    int lane = tid & 31, wrp = tid >> 5;
    if (lane < 16) {
        cs[wrp][tx*2]      = ps[0];  cs[wrp][tx*2 + 1]  = ps[1];
        cs2[wrp][tx*2]     = ps2[0]; cs2[wrp][tx*2 + 1] = ps2[1];
    }
    __syncthreads();
    if (tid < 32) {
        double s = 0.0, s2 = 0.0;
        #pragma unroll
        for (int w = 0; w < 8; w++) { s += cs[w][tid]; s2 += cs2[w][tid]; }
        atomicAdd(&g_dsum[ST_S2][tid], s);
        atomicAdd(&g_dsum2[ST_S2][tid], s2);
    }
}

// ---------------- attention: BN+leaky(s2) -> softmax over k -> combine + residual ----------------
__global__ __launch_bounds__(256)
void attn_kernel(const float* __restrict__ x, const float* __restrict__ s2,
                 const float* __restrict__ vb, const float* __restrict__ P,
                 const float* __restrict__ ge2, const float* __restrict__ be2,
                 const float* __restrict__ gpb, const float* __restrict__ bpb,
                 float* __restrict__ xattn)
{
    int bn = blockIdx.x;
    int t = threadIdx.x;
    __shared__ float soft[KNB][CPH + 1];
    __shared__ float ssa[CPH], ssc[CPH];
    __shared__ int sj[KNB];
    if (t < CPH) foldco(ST_S2, t, INV_M2, ge2, be2, ssa[t], ssc[t]);
    if (t >= 32 && t < 64) sj[t - 32] = g_idx[(size_t)bn * KNB + t - 32];
    float pa, pc;
    foldco(ST_PB, t, INV_M2, gpb, bpb, pa, pc);
    __syncthreads();

    size_t base = (size_t)bn * KNB * CPH;
    for (int e = t; e < KNB * CPH; e += 256) {
        int g = e & 31;
        float y = s2[base + e];
        soft[e >> 5][g] = lrelu(ssa[g] * y + ssc[g]);
    }
    __syncthreads();
    if (t < CPH) {
        float mx = -FLT_MAX;
        #pragma unroll
        for (int k = 0; k < KNB; k++) mx = fmaxf(mx, soft[k][t]);
        float s = 0.f;
        #pragma unroll
        for (int k = 0; k < KNB; k++) { float ev = expf(soft[k][t] - mx); soft[k][t] = ev; s += ev; }
        float inv = 1.f / s;
        #pragma unroll
        for (int k = 0; k < KNB; k++) soft[k][t] *= inv;
    }
    __syncthreads();

    int c = t, g = t >> 3;
    int b = bn >> 11;
    float pn = P[(size_t)bn * C_ + c];
    float acc = 0.f;
    #pragma unroll
    for (int k = 0; k < KNB; k++) {
        int jg = (b << 11) + sj[k];
        float posb = lrelu(pa * (P[(size_t)jg * C_ + c] - pn) + pc);
        acc += (vb[(size_t)jg * C_ + c] + posb) * soft[k][g];
    }
    size_t o = (size_t)bn * C_ + c;
    xattn[o] = x[o] + acc;
}

extern "C" void kernel_launch(void* const* d_in, const int* in_sizes, int n_in,
                              void* d_out, int out_size)
{
    const float* x   = (const float*)d_in[0];
    const float* pos = (const float*)d_in[1];
    const float* Wq  = (const float*)d_in[2];
    const float* gq  = (const float*)d_in[3];
    const float* bq  = (const float*)d_in[4];
    const float* Wk  = (const float*)d_in[5];
    const float* gk  = (const float*)d_in[6];
    const float* bk  = (const float*)d_in[7];
    const float* Wv  = (const float*)d_in[8];
    const float* gv  = (const float*)d_in[9];
    const float* bv  = (const float*)d_in[10];
    const float* Wpb = (const float*)d_in[11];
    const float* gpb = (const float*)d_in[12];
    const float* bpb = (const float*)d_in[13];
    const float* We1 = (const float*)d_in[14];
    const float* ge1 = (const float*)d_in[15];
    const float* be1 = (const float*)d_in[16];
    const float* We2 = (const float*)d_in[17];
    const float* ge2 = (const float*)d_in[18];
    const float* be2 = (const float*)d_in[19];
    const float* Wm1 = (const float*)d_in[20];
    const float* gm1 = (const float*)d_in[21];
    const float* bm1 = (const float*)d_in[22];
    const float* Wm2 = (const float*)d_in[23];
    const float* gm2 = (const float*)d_in[24];
    const float* bm2 = (const float*)d_in[25];
    float* out = (float*)d_out;

    void* p;
    float *qkv, *tmp, *sqv, *dist, *s1, *s2, *xatt;
    cudaGetSymbolAddress(&p, g_qkv);   qkv  = (float*)p;
    cudaGetSymbolAddress(&p, g_tmp4);  tmp  = (float*)p;
    cudaGetSymbolAddress(&p, g_sqv);   sqv  = (float*)p;
    cudaGetSymbolAddress(&p, g_dist);  dist = (float*)p;
    cudaGetSymbolAddress(&p, g_s1);    s1   = (float*)p;
    cudaGetSymbolAddress(&p, g_s2);    s2   = (float*)p;
    cudaGetSymbolAddress(&p, g_xattn); xatt = (float*)p;

    const size_t SL = (size_t)M1 * C_;
    float* t0 = tmp;
    float* t1 = tmp + SL;
    float* t2 = tmp + 2*SL;
    float* t3 = tmp + 3*SL;
    float* qb = qkv;
    float* kb = qkv + SL;
    float* vb = qkv + 2*SL;

    // 1. zero stats
    zero_all_stats<<<16, 256>>>();

    // 2. batched GEMM: q,k,v raw (stats fused) + P
    {
        Gemm4 g = { { x, x, x, pos }, { Wq, Wk, Wv, Wpb }, { t0, t1, t2, t3 },
                    { ST_Q, ST_K, ST_V, -1 } };
        gemm128_kernel<<<dim3(C_/128, M1/128, 4), 256>>>(g, C_, C_, 0, 0, 0);
    }
    // 3. BN apply q/k/v + fused sq
    bnqkv_kernel<<<3 * M1, 256>>>(tmp, qkv, gq, bq, gk, bk, gv, bv, sqv);
    // 4. symmetric dist
    dist_kernel<<<dim3(136, 1, B_), 256>>>(kb, sqv, dist);
    // 5. topk
    topk_kernel<<<M1, 256>>>(dist);
    // 6. posb stats
    pbstats_kernel<<<256, 256>>>(t3);
    // 7-8. vector path (folds computed in prologues, stats fused in epilogues)
    vec1_kernel<<<M2/128, 256>>>(qb, kb, t3, We1, gpb, bpb, s1);
    vec2_kernel<<<M2/128, 256>>>(s1, We2, ge1, be1, s2);
    // 9. attention + residual
    attn_kernel<<<M1, 256>>>(x, s2, vb, t3, ge2, be2, gpb, bpb, xatt);
    // 10-11. MLP
    {
        Gemm4 g = { { xatt, 0, 0, 0 }, { Wm1, 0, 0, 0 }, { t0, 0, 0, 0 },
                    { ST_M1, -1, -1, -1 } };
        gemm128_kernel<<<dim3(HID/128, M1/128, 1), 256>>>(g, HID, C_, 0, 0, 0);
    }
    {
        Gemm4 g = { { t0, 0, 0, 0 }, { Wm2, 0, 0, 0 }, { t2, 0, 0, 0 },
                    { ST_M2, -1, -1, -1 } };
        gemm128_kernel<<<dim3(C_/128, M1/128, 1), 256>>>(g, C_, HID, 1, gm1, bm1);
    }
    // 12. final BN+silu+residual
    bn_silu_res_apply<<<M1, 256>>>(t2, xatt, out, gm2, bm2);
}